// round 13
// baseline (speedup 1.0000x reference)
#include <cuda_runtime.h>
#include <cuda_fp16.h>
#include <math.h>
#include <stdint.h>

// GPT-2 small config (fixed by the problem)
#define NB   2
#define NT   1024
#define ND   768
#define NH   12
#define NL   12
#define NV   50257
#define NVP  50304                // NV padded to multiple of 128
#define NHD  64
#define NTOK (NB * NT)            // 2048 token rows
#define N3D  (3 * ND)             // 2304
#define N4D  (4 * ND)             // 3072

// ---------------------------------------------------------------------------
// Scratch (device globals; allocation inside kernel_launch is forbidden)
// ---------------------------------------------------------------------------
__device__ float g_x [NTOK * ND];                       // fp32 residual stream
__device__ __align__(16) __half g_h  [NTOK * ND];       // LN out
__device__ __align__(16) __half g_qkv[NTOK * N3D];
__device__ __align__(16) __half g_ao [NTOK * ND];       // attn out
__device__ __align__(16) __half g_fc1[NTOK * N4D];      // GELU out

// fp16 weights, transposed to [N,K] so GEMM B-operand is K-major like A
__device__ __align__(16) __half g_wteT [(size_t)NVP * ND];   // rows >= NV zeroed
__device__ __align__(16) __half g_qkvT [(size_t)NL * N3D * ND];
__device__ __align__(16) __half g_projT[(size_t)NL * ND * ND];
__device__ __align__(16) __half g_fc1T [(size_t)NL * N4D * ND];
__device__ __align__(16) __half g_fc2T [(size_t)NL * ND * N4D];

// ---------------------------------------------------------------------------
// Helpers
// ---------------------------------------------------------------------------
__device__ __forceinline__ uint32_t smem_u32(const void* p) {
    uint32_t a;
    asm("{ .reg .u64 t; cvta.to.shared.u64 t, %1; cvt.u32.u64 %0, t; }"
        : "=r"(a) : "l"(p));
    return a;
}
__device__ __forceinline__ void cp16(uint32_t dst, const void* src) {
    asm volatile("cp.async.cg.shared.global [%0], [%1], 16;"
                 :: "r"(dst), "l"(src) : "memory");
}
// fp16 mma, fp32 accumulate: D[16,8] += A[16,16] * B[16,8]
__device__ __forceinline__ void mma_f16(float* c, const uint32_t* a,
                                        const uint32_t* b) {
    asm volatile(
        "mma.sync.aligned.m16n8k16.row.col.f32.f16.f16.f32 "
        "{%0,%1,%2,%3}, {%4,%5,%6,%7}, {%8,%9}, {%0,%1,%2,%3};"
        : "+f"(c[0]), "+f"(c[1]), "+f"(c[2]), "+f"(c[3])
        : "r"(a[0]), "r"(a[1]), "r"(a[2]), "r"(a[3]), "r"(b[0]), "r"(b[1]));
}
__device__ __forceinline__ void ldm_x4(uint32_t* r, uint32_t addr) {
    asm volatile("ldmatrix.sync.aligned.m8n8.x4.shared.b16 {%0,%1,%2,%3}, [%4];"
                 : "=r"(r[0]), "=r"(r[1]), "=r"(r[2]), "=r"(r[3]) : "r"(addr));
}
__device__ __forceinline__ void ldm_x2(uint32_t* r, uint32_t addr) {
    asm volatile("ldmatrix.sync.aligned.m8n8.x2.shared.b16 {%0,%1}, [%2];"
                 : "=r"(r[0]), "=r"(r[1]) : "r"(addr));
}
__device__ __forceinline__ float gelu_f(float v) {
    return 0.5f * v * (1.0f + erff(v * 0.70710678118654752f));
}

// GEMM smem: 3 stages x (A tile + B tile); tile = 128 rows x 72 halfs (144B)
#define GTILE_B  (128 * 144)
#define SA_ST(s) ((s) * 2 * GTILE_B)
#define SB_ST(s) ((s) * 2 * GTILE_B + GTILE_B)
#define SMEM_GEMM (6 * GTILE_B)     // 110592 B (2 CTA/SM = 216KB)

// ---------------------------------------------------------------------------
// fp16 mma GEMM: C[M,N] = A[M,K] @ W  (Bt = W^T as [N,K] half, rows padded)
//   EPI: 0 +bias -> half (qkv); 1 +bias+res -> float; 2 +bias+GELU -> half;
//        3 none -> float (logits)
// Grid (M/128, ceil(N/128)), 256 threads. K%64==0, K/64>=2, M%128==0.
// ---------------------------------------------------------------------------
template <int EPI>
__global__ __launch_bounds__(256, 2) void tc_gemm_k(
    const __half* __restrict__ A, const __half* __restrict__ Bt,
    const float* __restrict__ bias, const float* __restrict__ res,
    void* __restrict__ Cv, int N, int K)
{
    extern __shared__ char smem[];
    const uint32_t sb = smem_u32(smem);
    const int tid  = threadIdx.x;
    const int lane = tid & 31;
    const int wid  = tid >> 5;
    const int wm   = (wid >> 2) * 64;
    const int wn   = (wid & 3) * 32;
    const int bm   = blockIdx.x * 128;
    const int bn   = blockIdx.y * 128;
    const int g    = lane >> 2;
    const int t    = lane & 3;
    const int T    = K >> 6;            // BK = 64 halfs

    auto load_stage = [&](int step, int s) {
        const __half* Ap = A  + (size_t)bm * K + step * 64;
        const __half* Bp = Bt + (size_t)bn * K + step * 64;
#pragma unroll
        for (int i = 0; i < 4; i++) {   // 1024 16B chunks per operand
            int f = tid + i * 256;
            int r = f >> 3, c = f & 7;
            cp16(sb + SA_ST(s) + r * 144 + c * 16, Ap + (size_t)r * K + c * 8);
            cp16(sb + SB_ST(s) + r * 144 + c * 16, Bp + (size_t)r * K + c * 8);
        }
        asm volatile("cp.async.commit_group;" ::: "memory");
    };

    float acc[4][4][4];
#pragma unroll
    for (int i = 0; i < 4; i++)
#pragma unroll
        for (int j = 0; j < 4; j++)
#pragma unroll
            for (int r = 0; r < 4; r++) acc[i][j][r] = 0.0f;

    load_stage(0, 0);
    load_stage(1, 1);

    // ldmatrix lane-address components
    const int arow = lane & 15;
    const int aoff = (lane >> 4) << 4;
    const int brow = ((lane & 16) >> 1) + (lane & 7);
    const int boff = (lane & 8) << 1;

    int s = 0;
    for (int ts = 0; ts < T; ts++) {
        if (ts + 1 < T) asm volatile("cp.async.wait_group 1;" ::: "memory");
        else            asm volatile("cp.async.wait_group 0;" ::: "memory");
        __syncthreads();
        if (ts + 2 < T) {
            int ns = s + 2;
            if (ns >= 3) ns -= 3;
            load_stage(ts + 2, ns);
        }

        const uint32_t saA = sb + SA_ST(s);
        const uint32_t sbB = sb + SB_ST(s);
#pragma unroll
        for (int kk = 0; kk < 4; kk++) {            // 4 x k16 steps = K64
            uint32_t af[4][4], bf[4][2];
#pragma unroll
            for (int mi = 0; mi < 4; mi++)
                ldm_x4(af[mi], saA + (wm + mi * 16 + arow) * 144 + aoff + kk * 32);
#pragma unroll
            for (int nj = 0; nj < 2; nj++) {
                uint32_t r4[4];
                ldm_x4(r4, sbB + (wn + nj * 16 + brow) * 144 + boff + kk * 32);
                bf[nj * 2][0]     = r4[0];
                bf[nj * 2][1]     = r4[1];
                bf[nj * 2 + 1][0] = r4[2];
                bf[nj * 2 + 1][1] = r4[3];
            }
#pragma unroll
            for (int mi = 0; mi < 4; mi++)
#pragma unroll
                for (int ni = 0; ni < 4; ni++)
                    mma_f16(acc[mi][ni], af[mi], bf[ni]);
        }
        if (++s == 3) s = 0;
    }

#pragma unroll
    for (int mi = 0; mi < 4; mi++) {
#pragma unroll
        for (int ni = 0; ni < 4; ni++) {
            const int gn = bn + wn + ni * 8 + t * 2;
#pragma unroll
            for (int r = 0; r < 2; r++) {
                const int gm = bm + wm + mi * 16 + g + r * 8;
                float v0 = acc[mi][ni][r * 2 + 0];
                float v1 = acc[mi][ni][r * 2 + 1];
                if (EPI != 3) {
                    v0 += bias[gn];
                    v1 += bias[gn + 1];
                }
                if (EPI == 2) {
                    v0 = gelu_f(v0);
                    v1 = gelu_f(v1);
                }
                if (EPI == 0 || EPI == 2) {         // half out, N%128==0
                    __half2 h = __floats2half2_rn(v0, v1);
                    *(__half2*)((__half*)Cv + (size_t)gm * N + gn) = h;
                } else if (EPI == 1) {              // float out + residual
                    float* C = (float*)Cv;
                    v0 += res[(size_t)gm * N + gn];
                    v1 += res[(size_t)gm * N + gn + 1];
                    C[(size_t)gm * N + gn]     = v0;
                    C[(size_t)gm * N + gn + 1] = v1;
                } else {                            // EPI 3: float out, ragged N
                    float* C = (float*)Cv;
                    if (gn < N)     C[(size_t)gm * N + gn]     = v0;
                    if (gn + 1 < N) C[(size_t)gm * N + gn + 1] = v1;
                }
            }
        }
    }
}

// ---------------------------------------------------------------------------
// Weight prep: transpose [K,N] -> [N,K] with fp16 conversion (layer via z)
// Tile: 64 k x 32 n. 128B-coalesced reads AND writes (half2 stores).
// ---------------------------------------------------------------------------
__global__ __launch_bounds__(256) void transpose_cvt_k(
    const float* __restrict__ in, __half* __restrict__ out,
    int Kd, int Nd, size_t in_ls, size_t out_ls)
{
    __shared__ float t[64][33];
    const float* ip = in  + blockIdx.z * in_ls;
    __half*      op = out + blockIdx.z * out_ls;
    int n0 = blockIdx.x * 32, k0 = blockIdx.y * 64;
#pragma unroll
    for (int i = 0; i < 8; i++) {
        int idx = threadIdx.x + i * 256;
        int k = idx >> 5, n = idx & 31;
        t[k][n] = ip[(size_t)(k0 + k) * Nd + n0 + n];
    }
    __syncthreads();
#pragma unroll
    for (int i = 0; i < 4; i++) {
        int idx = threadIdx.x + i * 256;
        int n = idx >> 5, kp = idx & 31;
        __half2 h = __floats2half2_rn(t[2 * kp][n], t[2 * kp + 1][n]);
        *(__half2*)&op[(size_t)(n0 + n) * Kd + k0 + 2 * kp] = h;
    }
}

// wte copy-convert: 8 elems/thread, 16B loads + 16B stores
__global__ __launch_bounds__(256) void wte_cvt_k(const float* __restrict__ wte) {
    size_t i = ((size_t)blockIdx.x * 256 + threadIdx.x) * 8;
    if (i >= (size_t)NVP * ND) return;
    int n = (int)(i / ND);                 // all 8 in same row (ND % 8 == 0)
    __half2 h[4];
    if (n < NV) {
        float4 a = *(const float4*)&wte[i];
        float4 b = *(const float4*)&wte[i + 4];
        h[0] = __floats2half2_rn(a.x, a.y);
        h[1] = __floats2half2_rn(a.z, a.w);
        h[2] = __floats2half2_rn(b.x, b.y);
        h[3] = __floats2half2_rn(b.z, b.w);
    } else {
        h[0] = h[1] = h[2] = h[3] = __floats2half2_rn(0.0f, 0.0f);
    }
    *(uint4*)&g_wteT[i] = *(uint4*)h;
}

// ---------------------------------------------------------------------------
// Embedding (fp32 residual stream)
// ---------------------------------------------------------------------------
__global__ __launch_bounds__(256) void embed_k(const int* __restrict__ idx,
                                               const float* __restrict__ wte,
                                               const float* __restrict__ pos) {
    int i = blockIdx.x * 256 + threadIdx.x;
    if (i >= NTOK * ND) return;
    int tok = i / ND;
    int d   = i - tok * ND;
    int t   = tok & (NT - 1);
    g_x[i] = wte[(size_t)idx[tok] * ND + d] + pos[t * ND + d];
}

// ---------------------------------------------------------------------------
// LayerNorm: single-pass warp-shuffle reduction; half output for fp16 mma
// ---------------------------------------------------------------------------
__global__ __launch_bounds__(256) void ln_k(const float* __restrict__ in,
                                            const float* __restrict__ gamma,
                                            const float* __restrict__ beta,
                                            __half* __restrict__ out) {
    int row = blockIdx.x;
    int tid = threadIdx.x;
    int lane = tid & 31, wid = tid >> 5;
    const float* x = in + (size_t)row * ND;
    float v0 = x[tid], v1 = x[tid + 256], v2 = x[tid + 512];

    float s  = v0 + v1 + v2;
    float sq = v0 * v0 + v1 * v1 + v2 * v2;
#pragma unroll
    for (int off = 16; off > 0; off >>= 1) {
        s  += __shfl_down_sync(0xffffffffu, s,  off);
        sq += __shfl_down_sync(0xffffffffu, sq, off);
    }
    __shared__ float ws[8], wq[8];
    if (lane == 0) { ws[wid] = s; wq[wid] = sq; }
    __syncthreads();
    float S = 0.0f, Q = 0.0f;
#pragma unroll
    for (int i = 0; i < 8; i++) { S += ws[i]; Q += wq[i]; }
    float m   = S * (1.0f / ND);
    float var = Q * (1.0f / ND) - m * m;
    float inv = rsqrtf(var + 1e-5f);

    __half* o = out + (size_t)row * ND;
    o[tid]       = __float2half_rn((v0 - m) * inv * gamma[tid]       + beta[tid]);
    o[tid + 256] = __float2half_rn((v1 - m) * inv * gamma[tid + 256] + beta[tid + 256]);
    o[tid + 512] = __float2half_rn((v2 - m) * inv * gamma[tid + 512] + beta[tid + 512]);
}

// ---------------------------------------------------------------------------
// Fused flash attention v2: one block per (128 q-rows, head), 256 threads =
// 8 warps x 16 q-rows. K/V double-buffered via cp.async groups — next tile's
// load issued BEFORE waiting on the current one (latency fully hidden).
// Q/P pitch 144B; K/V pitch 144B. ldmatrix fragment paths as validated.
// ---------------------------------------------------------------------------
#define FQB  (128 * 144)                 // Q / P tile bytes
#define FKB  (64 * 144)                  // K / V tile bytes
#define FLASH_SMEM (2 * FQB + 4 * FKB)   // 73728 B

__global__ __launch_bounds__(256, 2) void flash_attn_k() {
    int bh = blockIdx.y;
    int b  = bh / NH;
    int h  = bh - b * NH;
    int q0 = blockIdx.x * 128;

    extern __shared__ char fsm[];
    const uint32_t sq  = smem_u32(fsm);
    const uint32_t sp  = sq + FQB;
    const uint32_t skb = sq + 2 * FQB;          // 2 x K buffers
    const uint32_t svb = skb + 2 * FKB;         // 2 x V buffers
    uint32_t* PwS = (uint32_t*)(fsm + FQB);

    const int tid  = threadIdx.x;
    const int lane = tid & 31, wid = tid >> 5;
    const int g = lane >> 2, t = lane & 3;
    const int wm = wid * 16;
    const int arow = lane & 15;
    const int aoff = (lane >> 4) << 4;
    const int krow = lane & 7;
    const int koff = (lane & 8) << 1;

    const __half* base = g_qkv + (size_t)b * NT * N3D + h * NHD;

    // Q tile: 128 rows x 8 chunks = 1024 chunks / 256 threads
#pragma unroll
    for (int i = 0; i < 4; i++) {
        int f = tid + i * 256;
        int r = f >> 3, c = f & 7;
        cp16(sq + r * 144 + c * 16, base + (size_t)(q0 + r) * N3D + c * 8);
    }
    asm volatile("cp.async.commit_group;" ::: "memory");

    auto load_kv = [&](int k0, int sbuf) {
#pragma unroll
        for (int i = 0; i < 2; i++) {           // 512 chunks each / 256 threads
            int f = tid + i * 256;
            int r = f >> 3, c = f & 7;
            cp16(skb + sbuf * FKB + r * 144 + c * 16,
                 base + (size_t)(k0 + r) * N3D + ND + c * 8);
            cp16(svb + sbuf * FKB + r * 144 + c * 16,
                 base + (size_t)(k0 + r) * N3D + 2 * ND + c * 8);
        }
        asm volatile("cp.async.commit_group;" ::: "memory");
    };
    load_kv(0, 0);

    float acc[8][4];
#pragma unroll
    for (int i = 0; i < 8; i++)
#pragma unroll
        for (int r = 0; r < 4; r++) acc[i][r] = 0.0f;
    float m[2] = {-1e30f, -1e30f};
    float l[2] = {0.0f, 0.0f};

    const int TQ = (q0 >> 6) + 2;               // k-tiles covering q0+127

    for (int tt = 0; tt < TQ; tt++) {
        const int k0 = tt * 64;
        const int cb = tt & 1;
        __syncthreads();                        // buf cb's prior readers done
        if (tt + 1 < TQ) {
            load_kv(k0 + 64, cb ^ 1);           // prefetch next tile
            asm volatile("cp.async.wait_group 1;" ::: "memory");
        } else {
            asm volatile("cp.async.wait_group 0;" ::: "memory");
        }
        __syncthreads();                        // tile tt visible

        const uint32_t sk = skb + cb * FKB;
        const uint32_t sv = svb + cb * FKB;

        // S = Q.K^T (4 x k16 steps over 64 dims)
        float s[8][4];
#pragma unroll
        for (int i = 0; i < 8; i++)
#pragma unroll
            for (int r = 0; r < 4; r++) s[i][r] = 0.0f;
#pragma unroll
        for (int kk = 0; kk < 4; kk++) {
            uint32_t af[4];
            ldm_x4(af, sq + (wm + arow) * 144 + aoff + kk * 32);
#pragma unroll
            for (int ni = 0; ni < 8; ni++) {
                uint32_t bf[2];
                ldm_x2(bf, sk + (ni * 8 + krow) * 144 + koff + kk * 32);
                mma_f16(s[ni], af, bf);
            }
        }

        // scale + causal mask (only tiles that can intersect this warp's rows)
        const bool nearDiag = (k0 + 63 > q0 + wm);
#pragma unroll
        for (int ni = 0; ni < 8; ni++)
#pragma unroll
            for (int r = 0; r < 2; r++)
#pragma unroll
                for (int c = 0; c < 2; c++) {
                    float v = s[ni][r * 2 + c] * 0.125f;
                    if (nearDiag &&
                        (k0 + ni * 8 + t * 2 + c) > (q0 + wm + g + 8 * r))
                        v = -1e30f;
                    s[ni][r * 2 + c] = v;
                }

        // per-row tile max (quad reduce over t)
        float mt[2] = {-1e30f, -1e30f};
#pragma unroll
        for (int ni = 0; ni < 8; ni++)
#pragma unroll
            for (int r = 0; r < 2; r++)
                mt[r] = fmaxf(mt[r], fmaxf(s[ni][r * 2], s[ni][r * 2 + 1]));
#pragma unroll
        for (int r = 0; r < 2; r++) {
            mt[r] = fmaxf(mt[r], __shfl_xor_sync(0xffffffffu, mt[r], 1));
            mt[r] = fmaxf(mt[r], __shfl_xor_sync(0xffffffffu, mt[r], 2));
        }

        float mn[2], sc[2], ls[2] = {0.0f, 0.0f};
#pragma unroll
        for (int r = 0; r < 2; r++) {
            mn[r] = fmaxf(m[r], mt[r]);
            sc[r] = __expf(m[r] - mn[r]);
        }

        // P = exp(S - mn), fp16-rounded; straight to smem as half2
#pragma unroll
        for (int ni = 0; ni < 8; ni++)
#pragma unroll
            for (int r = 0; r < 2; r++) {
                float p0 = __expf(s[ni][r * 2 + 0] - mn[r]);
                float p1 = __expf(s[ni][r * 2 + 1] - mn[r]);
                __half2 hh = __floats2half2_rn(p0, p1);
                ls[r] += __low2float(hh) + __high2float(hh);
                PwS[(wm + g + 8 * r) * 36 + ni * 4 + t] = *(uint32_t*)&hh;
            }
#pragma unroll
        for (int r = 0; r < 2; r++) {
            ls[r] += __shfl_xor_sync(0xffffffffu, ls[r], 1);
            ls[r] += __shfl_xor_sync(0xffffffffu, ls[r], 2);
            l[r] = l[r] * sc[r] + ls[r];
            m[r] = mn[r];
        }

        // rescale O accumulator
#pragma unroll
        for (int ni = 0; ni < 8; ni++)
#pragma unroll
            for (int r = 0; r < 2; r++) {
                acc[ni][r * 2]     *= sc[r];
                acc[ni][r * 2 + 1] *= sc[r];
            }
        __syncthreads();                        // Ps visible

        // O += P.V  (A = P via ldmatrix.x4; B = V via ldmatrix.x2.trans)
#pragma unroll
        for (int kk = 0; kk < 4; kk++) {
            uint32_t af[4];
            ldm_x4(af, sp + (wm + arow) * 144 + aoff + kk * 32);
#pragma unroll
            for (int ni = 0; ni < 8; ni++) {
                uint32_t bf0, bf1;
                uint32_t addr = sv + (kk * 16 + (lane & 15)) * 144 + ni * 16;
                asm volatile(
                    "ldmatrix.sync.aligned.m8n8.x2.trans.shared.b16 {%0,%1}, [%2];"
                    : "=r"(bf0), "=r"(bf1) : "r"(addr));
                uint32_t bf[2] = {bf0, bf1};
                mma_f16(acc[ni], af, bf);
            }
        }
    }

    // O /= l ; write half (feeds proj GEMM)
    float inv[2] = {1.0f / l[0], 1.0f / l[1]};
    __half* o = g_ao + ((size_t)b * NT + q0) * ND + h * NHD;
#pragma unroll
    for (int ni = 0; ni < 8; ni++) {
        const int cn = ni * 8 + t * 2;
#pragma unroll
        for (int r = 0; r < 2; r++) {
            const int rm = wm + g + r * 8;
            __half2 hh = __floats2half2_rn(acc[ni][r * 2 + 0] * inv[r],
                                           acc[ni][r * 2 + 1] * inv[r]);
            *(__half2*)&o[(size_t)rm * ND + cn] = hh;
        }
    }
}

// ---------------------------------------------------------------------------
// Host driver — kernel launches only (graph-capturable)
// ---------------------------------------------------------------------------
extern "C" void kernel_launch(void* const* d_in, const int* in_sizes, int n_in,
                              void* d_out, int out_size) {
    const int*   idx   = (const int*)  d_in[0];
    const float* wte   = (const float*)d_in[1];
    const float* pos   = (const float*)d_in[2];
    const float* ln1g  = (const float*)d_in[3];
    const float* ln1b  = (const float*)d_in[4];
    const float* qkvw  = (const float*)d_in[5];
    const float* qkvb  = (const float*)d_in[6];
    const float* projw = (const float*)d_in[7];
    const float* projb = (const float*)d_in[8];
    const float* ln2g  = (const float*)d_in[9];
    const float* ln2b  = (const float*)d_in[10];
    const float* fc1w  = (const float*)d_in[11];
    const float* fc1b  = (const float*)d_in[12];
    const float* fc2w  = (const float*)d_in[13];
    const float* fc2b  = (const float*)d_in[14];
    const float* lnfg  = (const float*)d_in[15];
    const float* lnfb  = (const float*)d_in[16];

    float* px;
    __half *ph, *pao, *pfc1, *pqkv;
    __half *pwteT, *pqkvT, *pprojT, *pfc1T, *pfc2T;
    cudaGetSymbolAddress((void**)&px,    g_x);
    cudaGetSymbolAddress((void**)&ph,    g_h);
    cudaGetSymbolAddress((void**)&pao,   g_ao);
    cudaGetSymbolAddress((void**)&pfc1,  g_fc1);
    cudaGetSymbolAddress((void**)&pqkv,  g_qkv);
    cudaGetSymbolAddress((void**)&pwteT, g_wteT);
    cudaGetSymbolAddress((void**)&pqkvT, g_qkvT);
    cudaGetSymbolAddress((void**)&pprojT,g_projT);
    cudaGetSymbolAddress((void**)&pfc1T, g_fc1T);
    cudaGetSymbolAddress((void**)&pfc2T, g_fc2T);

    cudaFuncSetAttribute(tc_gemm_k<0>, cudaFuncAttributeMaxDynamicSharedMemorySize, SMEM_GEMM);
    cudaFuncSetAttribute(tc_gemm_k<1>, cudaFuncAttributeMaxDynamicSharedMemorySize, SMEM_GEMM);
    cudaFuncSetAttribute(tc_gemm_k<2>, cudaFuncAttributeMaxDynamicSharedMemorySize, SMEM_GEMM);
    cudaFuncSetAttribute(tc_gemm_k<3>, cudaFuncAttributeMaxDynamicSharedMemorySize, SMEM_GEMM);
    cudaFuncSetAttribute(flash_attn_k, cudaFuncAttributeMaxDynamicSharedMemorySize, FLASH_SMEM);

    // ---- weight prep (every replay; deterministic) ----
    wte_cvt_k<<<(int)(((size_t)NVP * ND / 8 + 255) / 256), 256>>>(wte);
    transpose_cvt_k<<<dim3(N3D / 32, ND / 64, NL), 256>>>(
        qkvw, pqkvT, ND, N3D, (size_t)ND * N3D, (size_t)N3D * ND);
    transpose_cvt_k<<<dim3(ND / 32, ND / 64, NL), 256>>>(
        projw, pprojT, ND, ND, (size_t)ND * ND, (size_t)ND * ND);
    transpose_cvt_k<<<dim3(N4D / 32, ND / 64, NL), 256>>>(
        fc1w, pfc1T, ND, N4D, (size_t)ND * N4D, (size_t)N4D * ND);
    transpose_cvt_k<<<dim3(ND / 32, N4D / 64, NL), 256>>>(
        fc2w, pfc2T, N4D, ND, (size_t)N4D * ND, (size_t)ND * N4D);

    embed_k<<<(NTOK * ND + 255) / 256, 256>>>(idx, wte, pos);

    for (int l = 0; l < NL; l++) {
        // --- attention half ---
        ln_k<<<NTOK, 256>>>(px, ln1g + (size_t)l * ND, ln1b + (size_t)l * ND, ph);

        tc_gemm_k<0><<<dim3(NTOK / 128, N3D / 128), 256, SMEM_GEMM>>>(
            ph, pqkvT + (size_t)l * N3D * ND, qkvb + (size_t)l * N3D,
            nullptr, pqkv, N3D, ND);

        flash_attn_k<<<dim3(NT / 128, NB * NH), 256, FLASH_SMEM>>>();

        tc_gemm_k<1><<<dim3(NTOK / 128, ND / 128), 256, SMEM_GEMM>>>(
            pao, pprojT + (size_t)l * ND * ND, projb + (size_t)l * ND,
            px, px, ND, ND);

        // --- MLP half ---
        ln_k<<<NTOK, 256>>>(px, ln2g + (size_t)l * ND, ln2b + (size_t)l * ND, ph);

        tc_gemm_k<2><<<dim3(NTOK / 128, N4D / 128), 256, SMEM_GEMM>>>(
            ph, pfc1T + (size_t)l * N4D * ND, fc1b + (size_t)l * N4D,
            nullptr, pfc1, N4D, ND);

        tc_gemm_k<1><<<dim3(NTOK / 128, ND / 128), 256, SMEM_GEMM>>>(
            pfc1, pfc2T + (size_t)l * ND * N4D, fc2b + (size_t)l * ND,
            px, px, ND, N4D);
    }

    // final LN + tied head
    ln_k<<<NTOK, 256>>>(px, lnfg, lnfb, ph);
    tc_gemm_k<3><<<dim3(NTOK / 128, NVP / 128), 256, SMEM_GEMM>>>(
        ph, pwteT, nullptr, nullptr, (float*)d_out, NV, ND);
}

// round 14
// speedup vs baseline: 1.0942x; 1.0942x over previous
#include <cuda_runtime.h>
#include <cuda_fp16.h>
#include <math.h>
#include <stdint.h>

// GPT-2 small config (fixed by the problem)
#define NB   2
#define NT   1024
#define ND   768
#define NH   12
#define NL   12
#define NV   50257
#define NVP  50304                // NV padded to multiple of 128
#define NHD  64
#define NTOK (NB * NT)            // 2048 token rows
#define N3D  (3 * ND)             // 2304
#define N4D  (4 * ND)             // 3072

// ---------------------------------------------------------------------------
// Scratch (device globals; allocation inside kernel_launch is forbidden)
// ---------------------------------------------------------------------------
__device__ float g_x [NTOK * ND];                       // fp32 residual stream
__device__ __align__(16) __half g_h  [NTOK * ND];       // LN out
__device__ __align__(16) __half g_qkv[NTOK * N3D];
__device__ __align__(16) __half g_ao [NTOK * ND];       // attn out
__device__ __align__(16) __half g_fc1[NTOK * N4D];      // GELU out

// fp16 weights, transposed to [N,K] so GEMM B-operand is K-major like A
__device__ __align__(16) __half g_wteT [(size_t)NVP * ND];   // rows >= NV zeroed
__device__ __align__(16) __half g_qkvT [(size_t)NL * N3D * ND];
__device__ __align__(16) __half g_projT[(size_t)NL * ND * ND];
__device__ __align__(16) __half g_fc1T [(size_t)NL * N4D * ND];
__device__ __align__(16) __half g_fc2T [(size_t)NL * ND * N4D];

// ---------------------------------------------------------------------------
// Helpers
// ---------------------------------------------------------------------------
__device__ __forceinline__ uint32_t smem_u32(const void* p) {
    uint32_t a;
    asm("{ .reg .u64 t; cvta.to.shared.u64 t, %1; cvt.u32.u64 %0, t; }"
        : "=r"(a) : "l"(p));
    return a;
}
__device__ __forceinline__ void cp16(uint32_t dst, const void* src) {
    asm volatile("cp.async.cg.shared.global [%0], [%1], 16;"
                 :: "r"(dst), "l"(src) : "memory");
}
// fp16 mma, fp32 accumulate: D[16,8] += A[16,16] * B[16,8]
__device__ __forceinline__ void mma_f16(float* c, const uint32_t* a,
                                        const uint32_t* b) {
    asm volatile(
        "mma.sync.aligned.m16n8k16.row.col.f32.f16.f16.f32 "
        "{%0,%1,%2,%3}, {%4,%5,%6,%7}, {%8,%9}, {%0,%1,%2,%3};"
        : "+f"(c[0]), "+f"(c[1]), "+f"(c[2]), "+f"(c[3])
        : "r"(a[0]), "r"(a[1]), "r"(a[2]), "r"(a[3]), "r"(b[0]), "r"(b[1]));
}
__device__ __forceinline__ void ldm_x4(uint32_t* r, uint32_t addr) {
    asm volatile("ldmatrix.sync.aligned.m8n8.x4.shared.b16 {%0,%1,%2,%3}, [%4];"
                 : "=r"(r[0]), "=r"(r[1]), "=r"(r[2]), "=r"(r[3]) : "r"(addr));
}
__device__ __forceinline__ void ldm_x2(uint32_t* r, uint32_t addr) {
    asm volatile("ldmatrix.sync.aligned.m8n8.x2.shared.b16 {%0,%1}, [%2];"
                 : "=r"(r[0]), "=r"(r[1]) : "r"(addr));
}
__device__ __forceinline__ float gelu_f(float v) {
    return 0.5f * v * (1.0f + erff(v * 0.70710678118654752f));
}

// GEMM smem: 3 stages x (A tile + B tile); tile = 128 rows x 72 halfs (144B)
#define GTILE_B  (128 * 144)
#define SA_ST(s) ((s) * 2 * GTILE_B)
#define SB_ST(s) ((s) * 2 * GTILE_B + GTILE_B)
#define SMEM_GEMM (6 * GTILE_B)     // 110592 B (2 CTA/SM = 216KB)

// ---------------------------------------------------------------------------
// fp16 mma GEMM (128x128 tile): C[M,N] = A[M,K] @ W (Bt = W^T as [N,K] half)
//   EPI: 0 +bias -> half (qkv); 1 +bias+res -> float; 2 +bias+GELU -> half;
//        3 none -> float (logits)
// Grid (M/128, ceil(N/128)), 256 threads. K%64==0, K/64>=2, M%128==0.
// ---------------------------------------------------------------------------
template <int EPI>
__global__ __launch_bounds__(256, 2) void tc_gemm_k(
    const __half* __restrict__ A, const __half* __restrict__ Bt,
    const float* __restrict__ bias, const float* __restrict__ res,
    void* __restrict__ Cv, int N, int K)
{
    extern __shared__ char smem[];
    const uint32_t sb = smem_u32(smem);
    const int tid  = threadIdx.x;
    const int lane = tid & 31;
    const int wid  = tid >> 5;
    const int wm   = (wid >> 2) * 64;
    const int wn   = (wid & 3) * 32;
    const int bm   = blockIdx.x * 128;
    const int bn   = blockIdx.y * 128;
    const int g    = lane >> 2;
    const int t    = lane & 3;
    const int T    = K >> 6;            // BK = 64 halfs

    auto load_stage = [&](int step, int s) {
        const __half* Ap = A  + (size_t)bm * K + step * 64;
        const __half* Bp = Bt + (size_t)bn * K + step * 64;
#pragma unroll
        for (int i = 0; i < 4; i++) {   // 1024 16B chunks per operand
            int f = tid + i * 256;
            int r = f >> 3, c = f & 7;
            cp16(sb + SA_ST(s) + r * 144 + c * 16, Ap + (size_t)r * K + c * 8);
            cp16(sb + SB_ST(s) + r * 144 + c * 16, Bp + (size_t)r * K + c * 8);
        }
        asm volatile("cp.async.commit_group;" ::: "memory");
    };

    float acc[4][4][4];
#pragma unroll
    for (int i = 0; i < 4; i++)
#pragma unroll
        for (int j = 0; j < 4; j++)
#pragma unroll
            for (int r = 0; r < 4; r++) acc[i][j][r] = 0.0f;

    load_stage(0, 0);
    load_stage(1, 1);

    // ldmatrix lane-address components
    const int arow = lane & 15;
    const int aoff = (lane >> 4) << 4;
    const int brow = ((lane & 16) >> 1) + (lane & 7);
    const int boff = (lane & 8) << 1;

    int s = 0;
    for (int ts = 0; ts < T; ts++) {
        if (ts + 1 < T) asm volatile("cp.async.wait_group 1;" ::: "memory");
        else            asm volatile("cp.async.wait_group 0;" ::: "memory");
        __syncthreads();
        if (ts + 2 < T) {
            int ns = s + 2;
            if (ns >= 3) ns -= 3;
            load_stage(ts + 2, ns);
        }

        const uint32_t saA = sb + SA_ST(s);
        const uint32_t sbB = sb + SB_ST(s);
#pragma unroll
        for (int kk = 0; kk < 4; kk++) {            // 4 x k16 steps = K64
            uint32_t af[4][4], bf[4][2];
#pragma unroll
            for (int mi = 0; mi < 4; mi++)
                ldm_x4(af[mi], saA + (wm + mi * 16 + arow) * 144 + aoff + kk * 32);
#pragma unroll
            for (int nj = 0; nj < 2; nj++) {
                uint32_t r4[4];
                ldm_x4(r4, sbB + (wn + nj * 16 + brow) * 144 + boff + kk * 32);
                bf[nj * 2][0]     = r4[0];
                bf[nj * 2][1]     = r4[1];
                bf[nj * 2 + 1][0] = r4[2];
                bf[nj * 2 + 1][1] = r4[3];
            }
#pragma unroll
            for (int mi = 0; mi < 4; mi++)
#pragma unroll
                for (int ni = 0; ni < 4; ni++)
                    mma_f16(acc[mi][ni], af[mi], bf[ni]);
        }
        if (++s == 3) s = 0;
    }

#pragma unroll
    for (int mi = 0; mi < 4; mi++) {
#pragma unroll
        for (int ni = 0; ni < 4; ni++) {
            const int gn = bn + wn + ni * 8 + t * 2;
#pragma unroll
            for (int r = 0; r < 2; r++) {
                const int gm = bm + wm + mi * 16 + g + r * 8;
                float v0 = acc[mi][ni][r * 2 + 0];
                float v1 = acc[mi][ni][r * 2 + 1];
                if (EPI != 3) {
                    v0 += bias[gn];
                    v1 += bias[gn + 1];
                }
                if (EPI == 2) {
                    v0 = gelu_f(v0);
                    v1 = gelu_f(v1);
                }
                if (EPI == 0 || EPI == 2) {         // half out, N%128==0
                    __half2 h = __floats2half2_rn(v0, v1);
                    *(__half2*)((__half*)Cv + (size_t)gm * N + gn) = h;
                } else if (EPI == 1) {              // float out + residual
                    float* C = (float*)Cv;
                    v0 += res[(size_t)gm * N + gn];
                    v1 += res[(size_t)gm * N + gn + 1];
                    C[(size_t)gm * N + gn]     = v0;
                    C[(size_t)gm * N + gn + 1] = v1;
                } else {                            // EPI 3: float out, ragged N
                    float* C = (float*)Cv;
                    if (gn < N)     C[(size_t)gm * N + gn]     = v0;
                    if (gn + 1 < N) C[(size_t)gm * N + gn + 1] = v1;
                }
            }
        }
    }
}

// ---------------------------------------------------------------------------
// 64x64-tile GEMM (+bias +residual -> float), for narrow-N GEMMs (proj, fc2)
// where 128x128 tiling leaves 2/3 of the chip idle. 128 threads, 4 warps 2x2,
// warp tile 32x32. Same k16 accumulation order as tc_gemm_k (bit-identical).
// Grid (M/64, N/64). Up to 4 CTA/SM.
// ---------------------------------------------------------------------------
#define G64_B   (64 * 144)
#define S64A(s) ((s) * 2 * G64_B)
#define S64B(s) ((s) * 2 * G64_B + G64_B)
#define SMEM_G64 (6 * G64_B)        // 55296 B

__global__ __launch_bounds__(128, 4) void tc_gemm64_k(
    const __half* __restrict__ A, const __half* __restrict__ Bt,
    const float* __restrict__ bias, const float* __restrict__ res,
    float* __restrict__ C, int N, int K)
{
    extern __shared__ char smem[];
    const uint32_t sb = smem_u32(smem);
    const int tid  = threadIdx.x;
    const int lane = tid & 31;
    const int wid  = tid >> 5;
    const int wm   = (wid >> 1) * 32;
    const int wn   = (wid & 1) * 32;
    const int bm   = blockIdx.x * 64;
    const int bn   = blockIdx.y * 64;
    const int g    = lane >> 2;
    const int t    = lane & 3;
    const int T    = K >> 6;

    auto load_stage = [&](int step, int s) {
        const __half* Ap = A  + (size_t)bm * K + step * 64;
        const __half* Bp = Bt + (size_t)bn * K + step * 64;
#pragma unroll
        for (int i = 0; i < 4; i++) {   // 512 16B chunks per operand
            int f = tid + i * 128;
            int r = f >> 3, c = f & 7;
            cp16(sb + S64A(s) + r * 144 + c * 16, Ap + (size_t)r * K + c * 8);
            cp16(sb + S64B(s) + r * 144 + c * 16, Bp + (size_t)r * K + c * 8);
        }
        asm volatile("cp.async.commit_group;" ::: "memory");
    };

    float acc[2][4][4];
#pragma unroll
    for (int i = 0; i < 2; i++)
#pragma unroll
        for (int j = 0; j < 4; j++)
#pragma unroll
            for (int r = 0; r < 4; r++) acc[i][j][r] = 0.0f;

    load_stage(0, 0);
    load_stage(1, 1);

    const int arow = lane & 15;
    const int aoff = (lane >> 4) << 4;
    const int brow = ((lane & 16) >> 1) + (lane & 7);
    const int boff = (lane & 8) << 1;

    int s = 0;
    for (int ts = 0; ts < T; ts++) {
        if (ts + 1 < T) asm volatile("cp.async.wait_group 1;" ::: "memory");
        else            asm volatile("cp.async.wait_group 0;" ::: "memory");
        __syncthreads();
        if (ts + 2 < T) {
            int ns = s + 2;
            if (ns >= 3) ns -= 3;
            load_stage(ts + 2, ns);
        }

        const uint32_t saA = sb + S64A(s);
        const uint32_t sbB = sb + S64B(s);
#pragma unroll
        for (int kk = 0; kk < 4; kk++) {
            uint32_t af[2][4], bf[4][2];
#pragma unroll
            for (int mi = 0; mi < 2; mi++)
                ldm_x4(af[mi], saA + (wm + mi * 16 + arow) * 144 + aoff + kk * 32);
#pragma unroll
            for (int nj = 0; nj < 2; nj++) {
                uint32_t r4[4];
                ldm_x4(r4, sbB + (wn + nj * 16 + brow) * 144 + boff + kk * 32);
                bf[nj * 2][0]     = r4[0];
                bf[nj * 2][1]     = r4[1];
                bf[nj * 2 + 1][0] = r4[2];
                bf[nj * 2 + 1][1] = r4[3];
            }
#pragma unroll
            for (int mi = 0; mi < 2; mi++)
#pragma unroll
                for (int ni = 0; ni < 4; ni++)
                    mma_f16(acc[mi][ni], af[mi], bf[ni]);
        }
        if (++s == 3) s = 0;
    }

#pragma unroll
    for (int mi = 0; mi < 2; mi++) {
#pragma unroll
        for (int ni = 0; ni < 4; ni++) {
            const int gn = bn + wn + ni * 8 + t * 2;
#pragma unroll
            for (int r = 0; r < 2; r++) {
                const int gm = bm + wm + mi * 16 + g + r * 8;
                float v0 = acc[mi][ni][r * 2 + 0] + bias[gn];
                float v1 = acc[mi][ni][r * 2 + 1] + bias[gn + 1];
                v0 += res[(size_t)gm * N + gn];
                v1 += res[(size_t)gm * N + gn + 1];
                C[(size_t)gm * N + gn]     = v0;
                C[(size_t)gm * N + gn + 1] = v1;
            }
        }
    }
}

// ---------------------------------------------------------------------------
// Weight prep: transpose [K,N] -> [N,K] with fp16 conversion (layer via z)
// Tile: 64 k x 32 n. 128B-coalesced reads AND writes (half2 stores).
// ---------------------------------------------------------------------------
__global__ __launch_bounds__(256) void transpose_cvt_k(
    const float* __restrict__ in, __half* __restrict__ out,
    int Kd, int Nd, size_t in_ls, size_t out_ls)
{
    __shared__ float t[64][33];
    const float* ip = in  + blockIdx.z * in_ls;
    __half*      op = out + blockIdx.z * out_ls;
    int n0 = blockIdx.x * 32, k0 = blockIdx.y * 64;
#pragma unroll
    for (int i = 0; i < 8; i++) {
        int idx = threadIdx.x + i * 256;
        int k = idx >> 5, n = idx & 31;
        t[k][n] = ip[(size_t)(k0 + k) * Nd + n0 + n];
    }
    __syncthreads();
#pragma unroll
    for (int i = 0; i < 4; i++) {
        int idx = threadIdx.x + i * 256;
        int n = idx >> 5, kp = idx & 31;
        __half2 h = __floats2half2_rn(t[2 * kp][n], t[2 * kp + 1][n]);
        *(__half2*)&op[(size_t)(n0 + n) * Kd + k0 + 2 * kp] = h;
    }
}

// wte copy-convert: 8 elems/thread, 16B loads + 16B stores
__global__ __launch_bounds__(256) void wte_cvt_k(const float* __restrict__ wte) {
    size_t i = ((size_t)blockIdx.x * 256 + threadIdx.x) * 8;
    if (i >= (size_t)NVP * ND) return;
    int n = (int)(i / ND);                 // all 8 in same row (ND % 8 == 0)
    __half2 h[4];
    if (n < NV) {
        float4 a = *(const float4*)&wte[i];
        float4 b = *(const float4*)&wte[i + 4];
        h[0] = __floats2half2_rn(a.x, a.y);
        h[1] = __floats2half2_rn(a.z, a.w);
        h[2] = __floats2half2_rn(b.x, b.y);
        h[3] = __floats2half2_rn(b.z, b.w);
    } else {
        h[0] = h[1] = h[2] = h[3] = __floats2half2_rn(0.0f, 0.0f);
    }
    *(uint4*)&g_wteT[i] = *(uint4*)h;
}

// ---------------------------------------------------------------------------
// Embedding (fp32 residual stream)
// ---------------------------------------------------------------------------
__global__ __launch_bounds__(256) void embed_k(const int* __restrict__ idx,
                                               const float* __restrict__ wte,
                                               const float* __restrict__ pos) {
    int i = blockIdx.x * 256 + threadIdx.x;
    if (i >= NTOK * ND) return;
    int tok = i / ND;
    int d   = i - tok * ND;
    int t   = tok & (NT - 1);
    g_x[i] = wte[(size_t)idx[tok] * ND + d] + pos[t * ND + d];
}

// ---------------------------------------------------------------------------
// LayerNorm: single-pass warp-shuffle reduction; half output for fp16 mma
// ---------------------------------------------------------------------------
__global__ __launch_bounds__(256) void ln_k(const float* __restrict__ in,
                                            const float* __restrict__ gamma,
                                            const float* __restrict__ beta,
                                            __half* __restrict__ out) {
    int row = blockIdx.x;
    int tid = threadIdx.x;
    int lane = tid & 31, wid = tid >> 5;
    const float* x = in + (size_t)row * ND;
    float v0 = x[tid], v1 = x[tid + 256], v2 = x[tid + 512];

    float s  = v0 + v1 + v2;
    float sq = v0 * v0 + v1 * v1 + v2 * v2;
#pragma unroll
    for (int off = 16; off > 0; off >>= 1) {
        s  += __shfl_down_sync(0xffffffffu, s,  off);
        sq += __shfl_down_sync(0xffffffffu, sq, off);
    }
    __shared__ float ws[8], wq[8];
    if (lane == 0) { ws[wid] = s; wq[wid] = sq; }
    __syncthreads();
    float S = 0.0f, Q = 0.0f;
#pragma unroll
    for (int i = 0; i < 8; i++) { S += ws[i]; Q += wq[i]; }
    float m   = S * (1.0f / ND);
    float var = Q * (1.0f / ND) - m * m;
    float inv = rsqrtf(var + 1e-5f);

    __half* o = out + (size_t)row * ND;
    o[tid]       = __float2half_rn((v0 - m) * inv * gamma[tid]       + beta[tid]);
    o[tid + 256] = __float2half_rn((v1 - m) * inv * gamma[tid + 256] + beta[tid + 256]);
    o[tid + 512] = __float2half_rn((v2 - m) * inv * gamma[tid + 512] + beta[tid + 512]);
}

// ---------------------------------------------------------------------------
// Fused flash attention (R12 proven version): one block per (64 q-rows, head).
// 128 threads = 4 warps x 16 q-rows. Q/P via ldmatrix.x4, K x2, V x2.trans.
// ---------------------------------------------------------------------------
#define FPW   36                         // pitch in words
#define FT_B  (64 * 144)                 // tile bytes
#define FLASH_SMEM (4 * FT_B)            // 36864 B

__global__ __launch_bounds__(128) void flash_attn_k() {
    int bh = blockIdx.y;
    int b  = bh / NH;
    int h  = bh - b * NH;
    int q0 = blockIdx.x * 64;

    extern __shared__ char fsm[];
    const uint32_t sq = smem_u32(fsm);
    const uint32_t sk = sq + FT_B;
    const uint32_t sp = sq + 2 * FT_B;
    const uint32_t sv = sq + 3 * FT_B;
    uint32_t* PwS = (uint32_t*)(fsm + 2 * FT_B);

    const int tid  = threadIdx.x;
    const int lane = tid & 31, wid = tid >> 5;
    const int g = lane >> 2, t = lane & 3;
    const int wm = wid * 16;
    const int arow = lane & 15;
    const int aoff = (lane >> 4) << 4;
    const int krow = lane & 7;
    const int koff = (lane & 8) << 1;

    const __half* base = g_qkv + (size_t)b * NT * N3D + h * NHD;

    // Q tile (resident all iterations): 512 16B chunks
#pragma unroll
    for (int i = 0; i < 4; i++) {
        int f = tid + i * 128;
        int r = f >> 3, c = f & 7;
        cp16(sq + r * 144 + c * 16, base + (size_t)(q0 + r) * N3D + c * 8);
    }
    asm volatile("cp.async.commit_group;" ::: "memory");

    float acc[8][4];
#pragma unroll
    for (int i = 0; i < 8; i++)
#pragma unroll
        for (int r = 0; r < 4; r++) acc[i][r] = 0.0f;
    float m[2] = {-1e30f, -1e30f};
    float l[2] = {0.0f, 0.0f};

    for (int k0 = 0; k0 <= q0; k0 += 64) {
        __syncthreads();                 // prior-iteration Ks/Vs/Ps reads done
#pragma unroll
        for (int i = 0; i < 4; i++) {
            int f = tid + i * 128;
            int r = f >> 3, c = f & 7;
            cp16(sk + r * 144 + c * 16,
                 base + (size_t)(k0 + r) * N3D + ND + c * 8);
            cp16(sv + r * 144 + c * 16,
                 base + (size_t)(k0 + r) * N3D + 2 * ND + c * 8);
        }
        asm volatile("cp.async.commit_group;" ::: "memory");
        asm volatile("cp.async.wait_group 0;" ::: "memory");
        __syncthreads();

        // S = Q.K^T (4 x k16 steps over 64 dims)
        float s[8][4];
#pragma unroll
        for (int i = 0; i < 8; i++)
#pragma unroll
            for (int r = 0; r < 4; r++) s[i][r] = 0.0f;
#pragma unroll
        for (int kk = 0; kk < 4; kk++) {
            uint32_t af[4];
            ldm_x4(af, sq + (wm + arow) * 144 + aoff + kk * 32);
#pragma unroll
            for (int ni = 0; ni < 8; ni++) {
                uint32_t bf[2];
                ldm_x2(bf, sk + (ni * 8 + krow) * 144 + koff + kk * 32);
                mma_f16(s[ni], af, bf);
            }
        }

        // scale + causal mask (diagonal tile only)
        const bool diag = (k0 == q0);
#pragma unroll
        for (int ni = 0; ni < 8; ni++)
#pragma unroll
            for (int r = 0; r < 2; r++)
#pragma unroll
                for (int c = 0; c < 2; c++) {
                    float v = s[ni][r * 2 + c] * 0.125f;
                    if (diag && (ni * 8 + t * 2 + c) > (wm + g + 8 * r))
                        v = -1e30f;
                    s[ni][r * 2 + c] = v;
                }

        // per-row tile max (quad reduce over t)
        float mt[2] = {-1e30f, -1e30f};
#pragma unroll
        for (int ni = 0; ni < 8; ni++)
#pragma unroll
            for (int r = 0; r < 2; r++)
                mt[r] = fmaxf(mt[r], fmaxf(s[ni][r * 2], s[ni][r * 2 + 1]));
#pragma unroll
        for (int r = 0; r < 2; r++) {
            mt[r] = fmaxf(mt[r], __shfl_xor_sync(0xffffffffu, mt[r], 1));
            mt[r] = fmaxf(mt[r], __shfl_xor_sync(0xffffffffu, mt[r], 2));
        }

        float mn[2], sc[2], ls[2] = {0.0f, 0.0f};
#pragma unroll
        for (int r = 0; r < 2; r++) {
            mn[r] = fmaxf(m[r], mt[r]);
            sc[r] = __expf(m[r] - mn[r]);
        }

        // P = exp(S - mn), fp16-rounded; write straight to smem as half2
#pragma unroll
        for (int ni = 0; ni < 8; ni++)
#pragma unroll
            for (int r = 0; r < 2; r++) {
                float p0 = __expf(s[ni][r * 2 + 0] - mn[r]);
                float p1 = __expf(s[ni][r * 2 + 1] - mn[r]);
                __half2 hh = __floats2half2_rn(p0, p1);
                ls[r] += __low2float(hh) + __high2float(hh);
                PwS[(wm + g + 8 * r) * FPW + ni * 4 + t] = *(uint32_t*)&hh;
            }
#pragma unroll
        for (int r = 0; r < 2; r++) {
            ls[r] += __shfl_xor_sync(0xffffffffu, ls[r], 1);
            ls[r] += __shfl_xor_sync(0xffffffffu, ls[r], 2);
            l[r] = l[r] * sc[r] + ls[r];
            m[r] = mn[r];
        }

        // rescale O accumulator
#pragma unroll
        for (int ni = 0; ni < 8; ni++)
#pragma unroll
            for (int r = 0; r < 2; r++) {
                acc[ni][r * 2]     *= sc[r];
                acc[ni][r * 2 + 1] *= sc[r];
            }
        __syncthreads();

        // O += P.V  (A = P via ldmatrix.x4; B = V via ldmatrix.x2.trans)
#pragma unroll
        for (int kk = 0; kk < 4; kk++) {
            uint32_t af[4];
            ldm_x4(af, sp + (wm + arow) * 144 + aoff + kk * 32);
#pragma unroll
            for (int ni = 0; ni < 8; ni++) {
                uint32_t bf0, bf1;
                uint32_t addr = sv + (kk * 16 + (lane & 15)) * 144 + ni * 16;
                asm volatile(
                    "ldmatrix.sync.aligned.m8n8.x2.trans.shared.b16 {%0,%1}, [%2];"
                    : "=r"(bf0), "=r"(bf1) : "r"(addr));
                uint32_t bf[2] = {bf0, bf1};
                mma_f16(acc[ni], af, bf);
            }
        }
    }

    // O /= l ; write half (feeds proj GEMM)
    float inv[2] = {1.0f / l[0], 1.0f / l[1]};
    __half* o = g_ao + ((size_t)b * NT + q0) * ND + h * NHD;
#pragma unroll
    for (int ni = 0; ni < 8; ni++) {
        const int cn = ni * 8 + t * 2;
#pragma unroll
        for (int r = 0; r < 2; r++) {
            const int rm = wm + g + r * 8;
            __half2 hh = __floats2half2_rn(acc[ni][r * 2 + 0] * inv[r],
                                           acc[ni][r * 2 + 1] * inv[r]);
            *(__half2*)&o[(size_t)rm * ND + cn] = hh;
        }
    }
}

// ---------------------------------------------------------------------------
// Host driver — kernel launches only (graph-capturable)
// ---------------------------------------------------------------------------
extern "C" void kernel_launch(void* const* d_in, const int* in_sizes, int n_in,
                              void* d_out, int out_size) {
    const int*   idx   = (const int*)  d_in[0];
    const float* wte   = (const float*)d_in[1];
    const float* pos   = (const float*)d_in[2];
    const float* ln1g  = (const float*)d_in[3];
    const float* ln1b  = (const float*)d_in[4];
    const float* qkvw  = (const float*)d_in[5];
    const float* qkvb  = (const float*)d_in[6];
    const float* projw = (const float*)d_in[7];
    const float* projb = (const float*)d_in[8];
    const float* ln2g  = (const float*)d_in[9];
    const float* ln2b  = (const float*)d_in[10];
    const float* fc1w  = (const float*)d_in[11];
    const float* fc1b  = (const float*)d_in[12];
    const float* fc2w  = (const float*)d_in[13];
    const float* fc2b  = (const float*)d_in[14];
    const float* lnfg  = (const float*)d_in[15];
    const float* lnfb  = (const float*)d_in[16];

    float* px;
    __half *ph, *pao, *pfc1, *pqkv;
    __half *pwteT, *pqkvT, *pprojT, *pfc1T, *pfc2T;
    cudaGetSymbolAddress((void**)&px,    g_x);
    cudaGetSymbolAddress((void**)&ph,    g_h);
    cudaGetSymbolAddress((void**)&pao,   g_ao);
    cudaGetSymbolAddress((void**)&pfc1,  g_fc1);
    cudaGetSymbolAddress((void**)&pqkv,  g_qkv);
    cudaGetSymbolAddress((void**)&pwteT, g_wteT);
    cudaGetSymbolAddress((void**)&pqkvT, g_qkvT);
    cudaGetSymbolAddress((void**)&pprojT,g_projT);
    cudaGetSymbolAddress((void**)&pfc1T, g_fc1T);
    cudaGetSymbolAddress((void**)&pfc2T, g_fc2T);

    cudaFuncSetAttribute(tc_gemm_k<0>, cudaFuncAttributeMaxDynamicSharedMemorySize, SMEM_GEMM);
    cudaFuncSetAttribute(tc_gemm_k<1>, cudaFuncAttributeMaxDynamicSharedMemorySize, SMEM_GEMM);
    cudaFuncSetAttribute(tc_gemm_k<2>, cudaFuncAttributeMaxDynamicSharedMemorySize, SMEM_GEMM);
    cudaFuncSetAttribute(tc_gemm_k<3>, cudaFuncAttributeMaxDynamicSharedMemorySize, SMEM_GEMM);
    cudaFuncSetAttribute(tc_gemm64_k,  cudaFuncAttributeMaxDynamicSharedMemorySize, SMEM_G64);
    cudaFuncSetAttribute(flash_attn_k, cudaFuncAttributeMaxDynamicSharedMemorySize, FLASH_SMEM);

    // ---- weight prep (every replay; deterministic) ----
    wte_cvt_k<<<(int)(((size_t)NVP * ND / 8 + 255) / 256), 256>>>(wte);
    transpose_cvt_k<<<dim3(N3D / 32, ND / 64, NL), 256>>>(
        qkvw, pqkvT, ND, N3D, (size_t)ND * N3D, (size_t)N3D * ND);
    transpose_cvt_k<<<dim3(ND / 32, ND / 64, NL), 256>>>(
        projw, pprojT, ND, ND, (size_t)ND * ND, (size_t)ND * ND);
    transpose_cvt_k<<<dim3(N4D / 32, ND / 64, NL), 256>>>(
        fc1w, pfc1T, ND, N4D, (size_t)ND * N4D, (size_t)N4D * ND);
    transpose_cvt_k<<<dim3(ND / 32, N4D / 64, NL), 256>>>(
        fc2w, pfc2T, N4D, ND, (size_t)N4D * ND, (size_t)ND * N4D);

    embed_k<<<(NTOK * ND + 255) / 256, 256>>>(idx, wte, pos);

    for (int l = 0; l < NL; l++) {
        // --- attention half ---
        ln_k<<<NTOK, 256>>>(px, ln1g + (size_t)l * ND, ln1b + (size_t)l * ND, ph);

        tc_gemm_k<0><<<dim3(NTOK / 128, N3D / 128), 256, SMEM_GEMM>>>(
            ph, pqkvT + (size_t)l * N3D * ND, qkvb + (size_t)l * N3D,
            nullptr, pqkv, N3D, ND);

        flash_attn_k<<<dim3(NT / 64, NB * NH), 128, FLASH_SMEM>>>();

        tc_gemm64_k<<<dim3(NTOK / 64, ND / 64), 128, SMEM_G64>>>(
            pao, pprojT + (size_t)l * ND * ND, projb + (size_t)l * ND,
            px, px, ND, ND);

        // --- MLP half ---
        ln_k<<<NTOK, 256>>>(px, ln2g + (size_t)l * ND, ln2b + (size_t)l * ND, ph);

        tc_gemm_k<2><<<dim3(NTOK / 128, N4D / 128), 256, SMEM_GEMM>>>(
            ph, pfc1T + (size_t)l * N4D * ND, fc1b + (size_t)l * N4D,
            nullptr, pfc1, N4D, ND);

        tc_gemm64_k<<<dim3(NTOK / 64, ND / 64), 128, SMEM_G64>>>(
            pfc1, pfc2T + (size_t)l * ND * N4D, fc2b + (size_t)l * ND,
            px, px, ND, N4D);
    }

    // final LN + tied head
    ln_k<<<NTOK, 256>>>(px, lnfg, lnfb, ph);
    tc_gemm_k<3><<<dim3(NTOK / 128, NVP / 128), 256, SMEM_GEMM>>>(
        ph, pwteT, nullptr, nullptr, (float*)d_out, NV, ND);
}

// round 15
// speedup vs baseline: 1.0947x; 1.0005x over previous
#include <cuda_runtime.h>
#include <cuda_fp16.h>
#include <math.h>
#include <stdint.h>

// GPT-2 small config (fixed by the problem)
#define NB   2
#define NT   1024
#define ND   768
#define NH   12
#define NL   12
#define NV   50257
#define NVP  50304                // NV padded to multiple of 128
#define NHD  64
#define NTOK (NB * NT)            // 2048 token rows
#define N3D  (3 * ND)             // 2304
#define N4D  (4 * ND)             // 3072

// ---------------------------------------------------------------------------
// Scratch (device globals; allocation inside kernel_launch is forbidden)
// ---------------------------------------------------------------------------
__device__ float g_x [NTOK * ND];                       // fp32 residual stream
__device__ __align__(16) __half g_h  [NTOK * ND];       // LN out
__device__ __align__(16) __half g_qkv[NTOK * N3D];
__device__ __align__(16) __half g_ao [NTOK * ND];       // attn out
__device__ __align__(16) __half g_fc1[NTOK * N4D];      // GELU out

// fp16 weights, transposed to [N,K] so GEMM B-operand is K-major like A
__device__ __align__(16) __half g_wteT [(size_t)NVP * ND];   // rows >= NV zeroed
__device__ __align__(16) __half g_qkvT [(size_t)NL * N3D * ND];
__device__ __align__(16) __half g_projT[(size_t)NL * ND * ND];
__device__ __align__(16) __half g_fc1T [(size_t)NL * N4D * ND];
__device__ __align__(16) __half g_fc2T [(size_t)NL * ND * N4D];

// ---------------------------------------------------------------------------
// Helpers
// ---------------------------------------------------------------------------
__device__ __forceinline__ uint32_t smem_u32(const void* p) {
    uint32_t a;
    asm("{ .reg .u64 t; cvta.to.shared.u64 t, %1; cvt.u32.u64 %0, t; }"
        : "=r"(a) : "l"(p));
    return a;
}
__device__ __forceinline__ void cp16(uint32_t dst, const void* src) {
    asm volatile("cp.async.cg.shared.global [%0], [%1], 16;"
                 :: "r"(dst), "l"(src) : "memory");
}
// fp16 mma, fp32 accumulate: D[16,8] += A[16,16] * B[16,8]
__device__ __forceinline__ void mma_f16(float* c, const uint32_t* a,
                                        const uint32_t* b) {
    asm volatile(
        "mma.sync.aligned.m16n8k16.row.col.f32.f16.f16.f32 "
        "{%0,%1,%2,%3}, {%4,%5,%6,%7}, {%8,%9}, {%0,%1,%2,%3};"
        : "+f"(c[0]), "+f"(c[1]), "+f"(c[2]), "+f"(c[3])
        : "r"(a[0]), "r"(a[1]), "r"(a[2]), "r"(a[3]), "r"(b[0]), "r"(b[1]));
}
__device__ __forceinline__ void ldm_x4(uint32_t* r, uint32_t addr) {
    asm volatile("ldmatrix.sync.aligned.m8n8.x4.shared.b16 {%0,%1,%2,%3}, [%4];"
                 : "=r"(r[0]), "=r"(r[1]), "=r"(r[2]), "=r"(r[3]) : "r"(addr));
}
__device__ __forceinline__ void ldm_x2(uint32_t* r, uint32_t addr) {
    asm volatile("ldmatrix.sync.aligned.m8n8.x2.shared.b16 {%0,%1}, [%2];"
                 : "=r"(r[0]), "=r"(r[1]) : "r"(addr));
}
__device__ __forceinline__ float gelu_f(float v) {
    return 0.5f * v * (1.0f + erff(v * 0.70710678118654752f));
}

// GEMM smem: 3 stages x (A tile + B tile); tile = 128 rows x 72 halfs (144B)
#define GTILE_B  (128 * 144)
#define SA_ST(s) ((s) * 2 * GTILE_B)
#define SB_ST(s) ((s) * 2 * GTILE_B + GTILE_B)
#define SMEM_GEMM (6 * GTILE_B)     // 110592 B (2 CTA/SM = 216KB)

// ---------------------------------------------------------------------------
// fp16 mma GEMM (128x128 tile): C[M,N] = A[M,K] @ W (Bt = W^T as [N,K] half)
//   EPI: 0 +bias -> half (qkv); 1 +bias+res -> float; 2 +bias+GELU -> half;
//        3 none -> float (logits)
// Grid (M/128, ceil(N/128)), 256 threads. K%64==0, K/64>=2, M%128==0.
// ---------------------------------------------------------------------------
template <int EPI>
__global__ __launch_bounds__(256, 2) void tc_gemm_k(
    const __half* __restrict__ A, const __half* __restrict__ Bt,
    const float* __restrict__ bias, const float* __restrict__ res,
    void* __restrict__ Cv, int N, int K)
{
    extern __shared__ char smem[];
    const uint32_t sb = smem_u32(smem);
    const int tid  = threadIdx.x;
    const int lane = tid & 31;
    const int wid  = tid >> 5;
    const int wm   = (wid >> 2) * 64;
    const int wn   = (wid & 3) * 32;
    const int bm   = blockIdx.x * 128;
    const int bn   = blockIdx.y * 128;
    const int g    = lane >> 2;
    const int t    = lane & 3;
    const int T    = K >> 6;            // BK = 64 halfs

    auto load_stage = [&](int step, int s) {
        const __half* Ap = A  + (size_t)bm * K + step * 64;
        const __half* Bp = Bt + (size_t)bn * K + step * 64;
#pragma unroll
        for (int i = 0; i < 4; i++) {   // 1024 16B chunks per operand
            int f = tid + i * 256;
            int r = f >> 3, c = f & 7;
            cp16(sb + SA_ST(s) + r * 144 + c * 16, Ap + (size_t)r * K + c * 8);
            cp16(sb + SB_ST(s) + r * 144 + c * 16, Bp + (size_t)r * K + c * 8);
        }
        asm volatile("cp.async.commit_group;" ::: "memory");
    };

    float acc[4][4][4];
#pragma unroll
    for (int i = 0; i < 4; i++)
#pragma unroll
        for (int j = 0; j < 4; j++)
#pragma unroll
            for (int r = 0; r < 4; r++) acc[i][j][r] = 0.0f;

    load_stage(0, 0);
    load_stage(1, 1);

    // ldmatrix lane-address components
    const int arow = lane & 15;
    const int aoff = (lane >> 4) << 4;
    const int brow = ((lane & 16) >> 1) + (lane & 7);
    const int boff = (lane & 8) << 1;

    int s = 0;
    for (int ts = 0; ts < T; ts++) {
        if (ts + 1 < T) asm volatile("cp.async.wait_group 1;" ::: "memory");
        else            asm volatile("cp.async.wait_group 0;" ::: "memory");
        __syncthreads();
        if (ts + 2 < T) {
            int ns = s + 2;
            if (ns >= 3) ns -= 3;
            load_stage(ts + 2, ns);
        }

        const uint32_t saA = sb + SA_ST(s);
        const uint32_t sbB = sb + SB_ST(s);
#pragma unroll
        for (int kk = 0; kk < 4; kk++) {            // 4 x k16 steps = K64
            uint32_t af[4][4], bf[4][2];
#pragma unroll
            for (int mi = 0; mi < 4; mi++)
                ldm_x4(af[mi], saA + (wm + mi * 16 + arow) * 144 + aoff + kk * 32);
#pragma unroll
            for (int nj = 0; nj < 2; nj++) {
                uint32_t r4[4];
                ldm_x4(r4, sbB + (wn + nj * 16 + brow) * 144 + boff + kk * 32);
                bf[nj * 2][0]     = r4[0];
                bf[nj * 2][1]     = r4[1];
                bf[nj * 2 + 1][0] = r4[2];
                bf[nj * 2 + 1][1] = r4[3];
            }
#pragma unroll
            for (int mi = 0; mi < 4; mi++)
#pragma unroll
                for (int ni = 0; ni < 4; ni++)
                    mma_f16(acc[mi][ni], af[mi], bf[ni]);
        }
        if (++s == 3) s = 0;
    }

#pragma unroll
    for (int mi = 0; mi < 4; mi++) {
#pragma unroll
        for (int ni = 0; ni < 4; ni++) {
            const int gn = bn + wn + ni * 8 + t * 2;
#pragma unroll
            for (int r = 0; r < 2; r++) {
                const int gm = bm + wm + mi * 16 + g + r * 8;
                float v0 = acc[mi][ni][r * 2 + 0];
                float v1 = acc[mi][ni][r * 2 + 1];
                if (EPI != 3) {
                    v0 += bias[gn];
                    v1 += bias[gn + 1];
                }
                if (EPI == 2) {
                    v0 = gelu_f(v0);
                    v1 = gelu_f(v1);
                }
                if (EPI == 0 || EPI == 2) {         // half out, N%128==0
                    __half2 h = __floats2half2_rn(v0, v1);
                    *(__half2*)((__half*)Cv + (size_t)gm * N + gn) = h;
                } else if (EPI == 1) {              // float out + residual
                    float* C = (float*)Cv;
                    v0 += res[(size_t)gm * N + gn];
                    v1 += res[(size_t)gm * N + gn + 1];
                    C[(size_t)gm * N + gn]     = v0;
                    C[(size_t)gm * N + gn + 1] = v1;
                } else {                            // EPI 3: float out, ragged N
                    float* C = (float*)Cv;
                    if (gn < N)     C[(size_t)gm * N + gn]     = v0;
                    if (gn + 1 < N) C[(size_t)gm * N + gn + 1] = v1;
                }
            }
        }
    }
}

// ---------------------------------------------------------------------------
// 64x64-tile GEMM for narrow/wave-quantized GEMMs (proj, fc2, fc1).
//   EPI: 1 +bias+res -> float; 2 +bias+GELU -> half
// 128 threads, 4 warps 2x2, warp tile 32x32. Same k16 accumulation order as
// tc_gemm_k (bit-identical results). Grid (M/64, N/64). Up to 4 CTA/SM.
// ---------------------------------------------------------------------------
#define G64_B   (64 * 144)
#define S64A(s) ((s) * 2 * G64_B)
#define S64B(s) ((s) * 2 * G64_B + G64_B)
#define SMEM_G64 (6 * G64_B)        // 55296 B

template <int EPI>
__global__ __launch_bounds__(128, 4) void tc_gemm64_k(
    const __half* __restrict__ A, const __half* __restrict__ Bt,
    const float* __restrict__ bias, const float* __restrict__ res,
    void* __restrict__ Cv, int N, int K)
{
    extern __shared__ char smem[];
    const uint32_t sb = smem_u32(smem);
    const int tid  = threadIdx.x;
    const int lane = tid & 31;
    const int wid  = tid >> 5;
    const int wm   = (wid >> 1) * 32;
    const int wn   = (wid & 1) * 32;
    const int bm   = blockIdx.x * 64;
    const int bn   = blockIdx.y * 64;
    const int g    = lane >> 2;
    const int t    = lane & 3;
    const int T    = K >> 6;

    auto load_stage = [&](int step, int s) {
        const __half* Ap = A  + (size_t)bm * K + step * 64;
        const __half* Bp = Bt + (size_t)bn * K + step * 64;
#pragma unroll
        for (int i = 0; i < 4; i++) {   // 512 16B chunks per operand
            int f = tid + i * 128;
            int r = f >> 3, c = f & 7;
            cp16(sb + S64A(s) + r * 144 + c * 16, Ap + (size_t)r * K + c * 8);
            cp16(sb + S64B(s) + r * 144 + c * 16, Bp + (size_t)r * K + c * 8);
        }
        asm volatile("cp.async.commit_group;" ::: "memory");
    };

    float acc[2][4][4];
#pragma unroll
    for (int i = 0; i < 2; i++)
#pragma unroll
        for (int j = 0; j < 4; j++)
#pragma unroll
            for (int r = 0; r < 4; r++) acc[i][j][r] = 0.0f;

    load_stage(0, 0);
    load_stage(1, 1);

    const int arow = lane & 15;
    const int aoff = (lane >> 4) << 4;
    const int brow = ((lane & 16) >> 1) + (lane & 7);
    const int boff = (lane & 8) << 1;

    int s = 0;
    for (int ts = 0; ts < T; ts++) {
        if (ts + 1 < T) asm volatile("cp.async.wait_group 1;" ::: "memory");
        else            asm volatile("cp.async.wait_group 0;" ::: "memory");
        __syncthreads();
        if (ts + 2 < T) {
            int ns = s + 2;
            if (ns >= 3) ns -= 3;
            load_stage(ts + 2, ns);
        }

        const uint32_t saA = sb + S64A(s);
        const uint32_t sbB = sb + S64B(s);
#pragma unroll
        for (int kk = 0; kk < 4; kk++) {
            uint32_t af[2][4], bf[4][2];
#pragma unroll
            for (int mi = 0; mi < 2; mi++)
                ldm_x4(af[mi], saA + (wm + mi * 16 + arow) * 144 + aoff + kk * 32);
#pragma unroll
            for (int nj = 0; nj < 2; nj++) {
                uint32_t r4[4];
                ldm_x4(r4, sbB + (wn + nj * 16 + brow) * 144 + boff + kk * 32);
                bf[nj * 2][0]     = r4[0];
                bf[nj * 2][1]     = r4[1];
                bf[nj * 2 + 1][0] = r4[2];
                bf[nj * 2 + 1][1] = r4[3];
            }
#pragma unroll
            for (int mi = 0; mi < 2; mi++)
#pragma unroll
                for (int ni = 0; ni < 4; ni++)
                    mma_f16(acc[mi][ni], af[mi], bf[ni]);
        }
        if (++s == 3) s = 0;
    }

#pragma unroll
    for (int mi = 0; mi < 2; mi++) {
#pragma unroll
        for (int ni = 0; ni < 4; ni++) {
            const int gn = bn + wn + ni * 8 + t * 2;
#pragma unroll
            for (int r = 0; r < 2; r++) {
                const int gm = bm + wm + mi * 16 + g + r * 8;
                float v0 = acc[mi][ni][r * 2 + 0] + bias[gn];
                float v1 = acc[mi][ni][r * 2 + 1] + bias[gn + 1];
                if (EPI == 1) {
                    float* C = (float*)Cv;
                    v0 += res[(size_t)gm * N + gn];
                    v1 += res[(size_t)gm * N + gn + 1];
                    C[(size_t)gm * N + gn]     = v0;
                    C[(size_t)gm * N + gn + 1] = v1;
                } else {                            // EPI 2: GELU -> half
                    __half2 h = __floats2half2_rn(gelu_f(v0), gelu_f(v1));
                    *(__half2*)((__half*)Cv + (size_t)gm * N + gn) = h;
                }
            }
        }
    }
}

// ---------------------------------------------------------------------------
// Weight prep: transpose [K,N] -> [N,K] with fp16 conversion (layer via z)
// Tile: 64 k x 32 n. 128B-coalesced reads AND writes (half2 stores).
// ---------------------------------------------------------------------------
__global__ __launch_bounds__(256) void transpose_cvt_k(
    const float* __restrict__ in, __half* __restrict__ out,
    int Kd, int Nd, size_t in_ls, size_t out_ls)
{
    __shared__ float t[64][33];
    const float* ip = in  + blockIdx.z * in_ls;
    __half*      op = out + blockIdx.z * out_ls;
    int n0 = blockIdx.x * 32, k0 = blockIdx.y * 64;
#pragma unroll
    for (int i = 0; i < 8; i++) {
        int idx = threadIdx.x + i * 256;
        int k = idx >> 5, n = idx & 31;
        t[k][n] = ip[(size_t)(k0 + k) * Nd + n0 + n];
    }
    __syncthreads();
#pragma unroll
    for (int i = 0; i < 4; i++) {
        int idx = threadIdx.x + i * 256;
        int n = idx >> 5, kp = idx & 31;
        __half2 h = __floats2half2_rn(t[2 * kp][n], t[2 * kp + 1][n]);
        *(__half2*)&op[(size_t)(n0 + n) * Kd + k0 + 2 * kp] = h;
    }
}

// wte copy-convert: 8 elems/thread, 16B loads + 16B stores
__global__ __launch_bounds__(256) void wte_cvt_k(const float* __restrict__ wte) {
    size_t i = ((size_t)blockIdx.x * 256 + threadIdx.x) * 8;
    if (i >= (size_t)NVP * ND) return;
    int n = (int)(i / ND);                 // all 8 in same row (ND % 8 == 0)
    __half2 h[4];
    if (n < NV) {
        float4 a = *(const float4*)&wte[i];
        float4 b = *(const float4*)&wte[i + 4];
        h[0] = __floats2half2_rn(a.x, a.y);
        h[1] = __floats2half2_rn(a.z, a.w);
        h[2] = __floats2half2_rn(b.x, b.y);
        h[3] = __floats2half2_rn(b.z, b.w);
    } else {
        h[0] = h[1] = h[2] = h[3] = __floats2half2_rn(0.0f, 0.0f);
    }
    *(uint4*)&g_wteT[i] = *(uint4*)h;
}

// ---------------------------------------------------------------------------
// Embedding (fp32 residual stream)
// ---------------------------------------------------------------------------
__global__ __launch_bounds__(256) void embed_k(const int* __restrict__ idx,
                                               const float* __restrict__ wte,
                                               const float* __restrict__ pos) {
    int i = blockIdx.x * 256 + threadIdx.x;
    if (i >= NTOK * ND) return;
    int tok = i / ND;
    int d   = i - tok * ND;
    int t   = tok & (NT - 1);
    g_x[i] = wte[(size_t)idx[tok] * ND + d] + pos[t * ND + d];
}

// ---------------------------------------------------------------------------
// LayerNorm: single-pass warp-shuffle reduction; half output for fp16 mma
// ---------------------------------------------------------------------------
__global__ __launch_bounds__(256) void ln_k(const float* __restrict__ in,
                                            const float* __restrict__ gamma,
                                            const float* __restrict__ beta,
                                            __half* __restrict__ out) {
    int row = blockIdx.x;
    int tid = threadIdx.x;
    int lane = tid & 31, wid = tid >> 5;
    const float* x = in + (size_t)row * ND;
    float v0 = x[tid], v1 = x[tid + 256], v2 = x[tid + 512];

    float s  = v0 + v1 + v2;
    float sq = v0 * v0 + v1 * v1 + v2 * v2;
#pragma unroll
    for (int off = 16; off > 0; off >>= 1) {
        s  += __shfl_down_sync(0xffffffffu, s,  off);
        sq += __shfl_down_sync(0xffffffffu, sq, off);
    }
    __shared__ float ws[8], wq[8];
    if (lane == 0) { ws[wid] = s; wq[wid] = sq; }
    __syncthreads();
    float S = 0.0f, Q = 0.0f;
#pragma unroll
    for (int i = 0; i < 8; i++) { S += ws[i]; Q += wq[i]; }
    float m   = S * (1.0f / ND);
    float var = Q * (1.0f / ND) - m * m;
    float inv = rsqrtf(var + 1e-5f);

    __half* o = out + (size_t)row * ND;
    o[tid]       = __float2half_rn((v0 - m) * inv * gamma[tid]       + beta[tid]);
    o[tid + 256] = __float2half_rn((v1 - m) * inv * gamma[tid + 256] + beta[tid + 256]);
    o[tid + 512] = __float2half_rn((v2 - m) * inv * gamma[tid + 512] + beta[tid + 512]);
}

// ---------------------------------------------------------------------------
// Fused flash attention (proven R12 version): one block per (64 q-rows, head).
// 128 threads = 4 warps x 16 q-rows. Q/P via ldmatrix.x4, K x2, V x2.trans.
// ---------------------------------------------------------------------------
#define FPW   36                         // pitch in words
#define FT_B  (64 * 144)                 // tile bytes
#define FLASH_SMEM (4 * FT_B)            // 36864 B

__global__ __launch_bounds__(128) void flash_attn_k() {
    int bh = blockIdx.y;
    int b  = bh / NH;
    int h  = bh - b * NH;
    int q0 = blockIdx.x * 64;

    extern __shared__ char fsm[];
    const uint32_t sq = smem_u32(fsm);
    const uint32_t sk = sq + FT_B;
    const uint32_t sp = sq + 2 * FT_B;
    const uint32_t sv = sq + 3 * FT_B;
    uint32_t* PwS = (uint32_t*)(fsm + 2 * FT_B);

    const int tid  = threadIdx.x;
    const int lane = tid & 31, wid = tid >> 5;
    const int g = lane >> 2, t = lane & 3;
    const int wm = wid * 16;
    const int arow = lane & 15;
    const int aoff = (lane >> 4) << 4;
    const int krow = lane & 7;
    const int koff = (lane & 8) << 1;

    const __half* base = g_qkv + (size_t)b * NT * N3D + h * NHD;

    // Q tile (resident all iterations): 512 16B chunks
#pragma unroll
    for (int i = 0; i < 4; i++) {
        int f = tid + i * 128;
        int r = f >> 3, c = f & 7;
        cp16(sq + r * 144 + c * 16, base + (size_t)(q0 + r) * N3D + c * 8);
    }
    asm volatile("cp.async.commit_group;" ::: "memory");

    float acc[8][4];
#pragma unroll
    for (int i = 0; i < 8; i++)
#pragma unroll
        for (int r = 0; r < 4; r++) acc[i][r] = 0.0f;
    float m[2] = {-1e30f, -1e30f};
    float l[2] = {0.0f, 0.0f};

    for (int k0 = 0; k0 <= q0; k0 += 64) {
        __syncthreads();                 // prior-iteration Ks/Vs/Ps reads done
#pragma unroll
        for (int i = 0; i < 4; i++) {
            int f = tid + i * 128;
            int r = f >> 3, c = f & 7;
            cp16(sk + r * 144 + c * 16,
                 base + (size_t)(k0 + r) * N3D + ND + c * 8);
            cp16(sv + r * 144 + c * 16,
                 base + (size_t)(k0 + r) * N3D + 2 * ND + c * 8);
        }
        asm volatile("cp.async.commit_group;" ::: "memory");
        asm volatile("cp.async.wait_group 0;" ::: "memory");
        __syncthreads();

        // S = Q.K^T (4 x k16 steps over 64 dims)
        float s[8][4];
#pragma unroll
        for (int i = 0; i < 8; i++)
#pragma unroll
            for (int r = 0; r < 4; r++) s[i][r] = 0.0f;
#pragma unroll
        for (int kk = 0; kk < 4; kk++) {
            uint32_t af[4];
            ldm_x4(af, sq + (wm + arow) * 144 + aoff + kk * 32);
#pragma unroll
            for (int ni = 0; ni < 8; ni++) {
                uint32_t bf[2];
                ldm_x2(bf, sk + (ni * 8 + krow) * 144 + koff + kk * 32);
                mma_f16(s[ni], af, bf);
            }
        }

        // scale + causal mask (diagonal tile only)
        const bool diag = (k0 == q0);
#pragma unroll
        for (int ni = 0; ni < 8; ni++)
#pragma unroll
            for (int r = 0; r < 2; r++)
#pragma unroll
                for (int c = 0; c < 2; c++) {
                    float v = s[ni][r * 2 + c] * 0.125f;
                    if (diag && (ni * 8 + t * 2 + c) > (wm + g + 8 * r))
                        v = -1e30f;
                    s[ni][r * 2 + c] = v;
                }

        // per-row tile max (quad reduce over t)
        float mt[2] = {-1e30f, -1e30f};
#pragma unroll
        for (int ni = 0; ni < 8; ni++)
#pragma unroll
            for (int r = 0; r < 2; r++)
                mt[r] = fmaxf(mt[r], fmaxf(s[ni][r * 2], s[ni][r * 2 + 1]));
#pragma unroll
        for (int r = 0; r < 2; r++) {
            mt[r] = fmaxf(mt[r], __shfl_xor_sync(0xffffffffu, mt[r], 1));
            mt[r] = fmaxf(mt[r], __shfl_xor_sync(0xffffffffu, mt[r], 2));
        }

        float mn[2], sc[2], ls[2] = {0.0f, 0.0f};
#pragma unroll
        for (int r = 0; r < 2; r++) {
            mn[r] = fmaxf(m[r], mt[r]);
            sc[r] = __expf(m[r] - mn[r]);
        }

        // P = exp(S - mn), fp16-rounded; write straight to smem as half2
#pragma unroll
        for (int ni = 0; ni < 8; ni++)
#pragma unroll
            for (int r = 0; r < 2; r++) {
                float p0 = __expf(s[ni][r * 2 + 0] - mn[r]);
                float p1 = __expf(s[ni][r * 2 + 1] - mn[r]);
                __half2 hh = __floats2half2_rn(p0, p1);
                ls[r] += __low2float(hh) + __high2float(hh);
                PwS[(wm + g + 8 * r) * FPW + ni * 4 + t] = *(uint32_t*)&hh;
            }
#pragma unroll
        for (int r = 0; r < 2; r++) {
            ls[r] += __shfl_xor_sync(0xffffffffu, ls[r], 1);
            ls[r] += __shfl_xor_sync(0xffffffffu, ls[r], 2);
            l[r] = l[r] * sc[r] + ls[r];
            m[r] = mn[r];
        }

        // rescale O accumulator
#pragma unroll
        for (int ni = 0; ni < 8; ni++)
#pragma unroll
            for (int r = 0; r < 2; r++) {
                acc[ni][r * 2]     *= sc[r];
                acc[ni][r * 2 + 1] *= sc[r];
            }
        __syncthreads();

        // O += P.V  (A = P via ldmatrix.x4; B = V via ldmatrix.x2.trans)
#pragma unroll
        for (int kk = 0; kk < 4; kk++) {
            uint32_t af[4];
            ldm_x4(af, sp + (wm + arow) * 144 + aoff + kk * 32);
#pragma unroll
            for (int ni = 0; ni < 8; ni++) {
                uint32_t bf0, bf1;
                uint32_t addr = sv + (kk * 16 + (lane & 15)) * 144 + ni * 16;
                asm volatile(
                    "ldmatrix.sync.aligned.m8n8.x2.trans.shared.b16 {%0,%1}, [%2];"
                    : "=r"(bf0), "=r"(bf1) : "r"(addr));
                uint32_t bf[2] = {bf0, bf1};
                mma_f16(acc[ni], af, bf);
            }
        }
    }

    // O /= l ; write half (feeds proj GEMM)
    float inv[2] = {1.0f / l[0], 1.0f / l[1]};
    __half* o = g_ao + ((size_t)b * NT + q0) * ND + h * NHD;
#pragma unroll
    for (int ni = 0; ni < 8; ni++) {
        const int cn = ni * 8 + t * 2;
#pragma unroll
        for (int r = 0; r < 2; r++) {
            const int rm = wm + g + r * 8;
            __half2 hh = __floats2half2_rn(acc[ni][r * 2 + 0] * inv[r],
                                           acc[ni][r * 2 + 1] * inv[r]);
            *(__half2*)&o[(size_t)rm * ND + cn] = hh;
        }
    }
}

// ---------------------------------------------------------------------------
// Host driver — kernel launches only (graph-capturable)
// ---------------------------------------------------------------------------
extern "C" void kernel_launch(void* const* d_in, const int* in_sizes, int n_in,
                              void* d_out, int out_size) {
    const int*   idx   = (const int*)  d_in[0];
    const float* wte   = (const float*)d_in[1];
    const float* pos   = (const float*)d_in[2];
    const float* ln1g  = (const float*)d_in[3];
    const float* ln1b  = (const float*)d_in[4];
    const float* qkvw  = (const float*)d_in[5];
    const float* qkvb  = (const float*)d_in[6];
    const float* projw = (const float*)d_in[7];
    const float* projb = (const float*)d_in[8];
    const float* ln2g  = (const float*)d_in[9];
    const float* ln2b  = (const float*)d_in[10];
    const float* fc1w  = (const float*)d_in[11];
    const float* fc1b  = (const float*)d_in[12];
    const float* fc2w  = (const float*)d_in[13];
    const float* fc2b  = (const float*)d_in[14];
    const float* lnfg  = (const float*)d_in[15];
    const float* lnfb  = (const float*)d_in[16];

    float* px;
    __half *ph, *pao, *pfc1, *pqkv;
    __half *pwteT, *pqkvT, *pprojT, *pfc1T, *pfc2T;
    cudaGetSymbolAddress((void**)&px,    g_x);
    cudaGetSymbolAddress((void**)&ph,    g_h);
    cudaGetSymbolAddress((void**)&pao,   g_ao);
    cudaGetSymbolAddress((void**)&pfc1,  g_fc1);
    cudaGetSymbolAddress((void**)&pqkv,  g_qkv);
    cudaGetSymbolAddress((void**)&pwteT, g_wteT);
    cudaGetSymbolAddress((void**)&pqkvT, g_qkvT);
    cudaGetSymbolAddress((void**)&pprojT,g_projT);
    cudaGetSymbolAddress((void**)&pfc1T, g_fc1T);
    cudaGetSymbolAddress((void**)&pfc2T, g_fc2T);

    cudaFuncSetAttribute(tc_gemm_k<0>, cudaFuncAttributeMaxDynamicSharedMemorySize, SMEM_GEMM);
    cudaFuncSetAttribute(tc_gemm_k<1>, cudaFuncAttributeMaxDynamicSharedMemorySize, SMEM_GEMM);
    cudaFuncSetAttribute(tc_gemm_k<2>, cudaFuncAttributeMaxDynamicSharedMemorySize, SMEM_GEMM);
    cudaFuncSetAttribute(tc_gemm_k<3>, cudaFuncAttributeMaxDynamicSharedMemorySize, SMEM_GEMM);
    cudaFuncSetAttribute(tc_gemm64_k<1>, cudaFuncAttributeMaxDynamicSharedMemorySize, SMEM_G64);
    cudaFuncSetAttribute(tc_gemm64_k<2>, cudaFuncAttributeMaxDynamicSharedMemorySize, SMEM_G64);
    cudaFuncSetAttribute(flash_attn_k, cudaFuncAttributeMaxDynamicSharedMemorySize, FLASH_SMEM);

    // ---- weight prep (every replay; deterministic) ----
    wte_cvt_k<<<(int)(((size_t)NVP * ND / 8 + 255) / 256), 256>>>(wte);
    transpose_cvt_k<<<dim3(N3D / 32, ND / 64, NL), 256>>>(
        qkvw, pqkvT, ND, N3D, (size_t)ND * N3D, (size_t)N3D * ND);
    transpose_cvt_k<<<dim3(ND / 32, ND / 64, NL), 256>>>(
        projw, pprojT, ND, ND, (size_t)ND * ND, (size_t)ND * ND);
    transpose_cvt_k<<<dim3(N4D / 32, ND / 64, NL), 256>>>(
        fc1w, pfc1T, ND, N4D, (size_t)ND * N4D, (size_t)N4D * ND);
    transpose_cvt_k<<<dim3(ND / 32, N4D / 64, NL), 256>>>(
        fc2w, pfc2T, N4D, ND, (size_t)N4D * ND, (size_t)ND * N4D);

    embed_k<<<(NTOK * ND + 255) / 256, 256>>>(idx, wte, pos);

    for (int l = 0; l < NL; l++) {
        // --- attention half ---
        ln_k<<<NTOK, 256>>>(px, ln1g + (size_t)l * ND, ln1b + (size_t)l * ND, ph);

        tc_gemm_k<0><<<dim3(NTOK / 128, N3D / 128), 256, SMEM_GEMM>>>(
            ph, pqkvT + (size_t)l * N3D * ND, qkvb + (size_t)l * N3D,
            nullptr, pqkv, N3D, ND);

        flash_attn_k<<<dim3(NT / 64, NB * NH), 128, FLASH_SMEM>>>();

        tc_gemm64_k<1><<<dim3(NTOK / 64, ND / 64), 128, SMEM_G64>>>(
            pao, pprojT + (size_t)l * ND * ND, projb + (size_t)l * ND,
            px, px, ND, ND);

        // --- MLP half ---
        ln_k<<<NTOK, 256>>>(px, ln2g + (size_t)l * ND, ln2b + (size_t)l * ND, ph);

        tc_gemm64_k<2><<<dim3(NTOK / 64, N4D / 64), 128, SMEM_G64>>>(
            ph, pfc1T + (size_t)l * N4D * ND, fc1b + (size_t)l * N4D,
            nullptr, pfc1, N4D, ND);

        tc_gemm64_k<1><<<dim3(NTOK / 64, ND / 64), 128, SMEM_G64>>>(
            pfc1, pfc2T + (size_t)l * ND * N4D, fc2b + (size_t)l * ND,
            px, px, ND, N4D);
    }

    // final LN + tied head
    ln_k<<<NTOK, 256>>>(px, lnfg, lnfb, ph);
    tc_gemm_k<3><<<dim3(NTOK / 128, NVP / 128), 256, SMEM_GEMM>>>(
        ph, pwteT, nullptr, nullptr, (float*)d_out, NV, ND);
}

// round 16
// speedup vs baseline: 1.1039x; 1.0084x over previous
#include <cuda_runtime.h>
#include <cuda_fp16.h>
#include <math.h>
#include <stdint.h>

// GPT-2 small config (fixed by the problem)
#define NB   2
#define NT   1024
#define ND   768
#define NH   12
#define NL   12
#define NV   50257
#define NVP  50304                // NV padded to multiple of 128
#define NHD  64
#define NTOK (NB * NT)            // 2048 token rows
#define N3D  (3 * ND)             // 2304
#define N4D  (4 * ND)             // 3072

// ---------------------------------------------------------------------------
// Scratch (device globals; allocation inside kernel_launch is forbidden)
// ---------------------------------------------------------------------------
__device__ float g_x [NTOK * ND];                       // fp32 residual stream
__device__ __align__(16) __half g_h  [NTOK * ND];       // LN out
__device__ __align__(16) __half g_qkv[NTOK * N3D];
__device__ __align__(16) __half g_ao [NTOK * ND];       // attn out
__device__ __align__(16) __half g_fc1[NTOK * N4D];      // GELU out

// fp16 weights, transposed to [N,K] so GEMM B-operand is K-major like A
__device__ __align__(16) __half g_wteT [(size_t)NVP * ND];   // rows >= NV zeroed
__device__ __align__(16) __half g_qkvT [(size_t)NL * N3D * ND];
__device__ __align__(16) __half g_projT[(size_t)NL * ND * ND];
__device__ __align__(16) __half g_fc1T [(size_t)NL * N4D * ND];
__device__ __align__(16) __half g_fc2T [(size_t)NL * ND * N4D];

// ---------------------------------------------------------------------------
// Helpers
// ---------------------------------------------------------------------------
__device__ __forceinline__ uint32_t smem_u32(const void* p) {
    uint32_t a;
    asm("{ .reg .u64 t; cvta.to.shared.u64 t, %1; cvt.u32.u64 %0, t; }"
        : "=r"(a) : "l"(p));
    return a;
}
__device__ __forceinline__ void cp16(uint32_t dst, const void* src) {
    asm volatile("cp.async.cg.shared.global [%0], [%1], 16;"
                 :: "r"(dst), "l"(src) : "memory");
}
// fp16 mma, fp32 accumulate: D[16,8] += A[16,16] * B[16,8]
__device__ __forceinline__ void mma_f16(float* c, const uint32_t* a,
                                        const uint32_t* b) {
    asm volatile(
        "mma.sync.aligned.m16n8k16.row.col.f32.f16.f16.f32 "
        "{%0,%1,%2,%3}, {%4,%5,%6,%7}, {%8,%9}, {%0,%1,%2,%3};"
        : "+f"(c[0]), "+f"(c[1]), "+f"(c[2]), "+f"(c[3])
        : "r"(a[0]), "r"(a[1]), "r"(a[2]), "r"(a[3]), "r"(b[0]), "r"(b[1]));
}
__device__ __forceinline__ void ldm_x4(uint32_t* r, uint32_t addr) {
    asm volatile("ldmatrix.sync.aligned.m8n8.x4.shared.b16 {%0,%1,%2,%3}, [%4];"
                 : "=r"(r[0]), "=r"(r[1]), "=r"(r[2]), "=r"(r[3]) : "r"(addr));
}
__device__ __forceinline__ void ldm_x2(uint32_t* r, uint32_t addr) {
    asm volatile("ldmatrix.sync.aligned.m8n8.x2.shared.b16 {%0,%1}, [%2];"
                 : "=r"(r[0]), "=r"(r[1]) : "r"(addr));
}
__device__ __forceinline__ float gelu_f(float v) {
    return 0.5f * v * (1.0f + erff(v * 0.70710678118654752f));
}

// GEMM smem: 3 stages x (A tile + B tile); tile = 128 rows x 72 halfs (144B)
#define GTILE_B  (128 * 144)
#define SA_ST(s) ((s) * 2 * GTILE_B)
#define SB_ST(s) ((s) * 2 * GTILE_B + GTILE_B)
#define SMEM_GEMM (6 * GTILE_B)     // 110592 B (2 CTA/SM = 216KB)

// ---------------------------------------------------------------------------
// fp16 mma GEMM (128x128 tile): C[M,N] = A[M,K] @ W (Bt = W^T as [N,K] half)
//   EPI: 0 +bias -> half (qkv); 1 +bias+res -> float; 2 +bias+GELU -> half;
//        3 none -> float (logits)
// Grid (M/128, ceil(N/128)), 256 threads. K%64==0, K/64>=2, M%128==0.
// ---------------------------------------------------------------------------
template <int EPI>
__global__ __launch_bounds__(256, 2) void tc_gemm_k(
    const __half* __restrict__ A, const __half* __restrict__ Bt,
    const float* __restrict__ bias, const float* __restrict__ res,
    void* __restrict__ Cv, int N, int K)
{
    extern __shared__ char smem[];
    const uint32_t sb = smem_u32(smem);
    const int tid  = threadIdx.x;
    const int lane = tid & 31;
    const int wid  = tid >> 5;
    const int wm   = (wid >> 2) * 64;
    const int wn   = (wid & 3) * 32;
    const int bm   = blockIdx.x * 128;
    const int bn   = blockIdx.y * 128;
    const int g    = lane >> 2;
    const int t    = lane & 3;
    const int T    = K >> 6;            // BK = 64 halfs

    auto load_stage = [&](int step, int s) {
        const __half* Ap = A  + (size_t)bm * K + step * 64;
        const __half* Bp = Bt + (size_t)bn * K + step * 64;
#pragma unroll
        for (int i = 0; i < 4; i++) {   // 1024 16B chunks per operand
            int f = tid + i * 256;
            int r = f >> 3, c = f & 7;
            cp16(sb + SA_ST(s) + r * 144 + c * 16, Ap + (size_t)r * K + c * 8);
            cp16(sb + SB_ST(s) + r * 144 + c * 16, Bp + (size_t)r * K + c * 8);
        }
        asm volatile("cp.async.commit_group;" ::: "memory");
    };

    float acc[4][4][4];
#pragma unroll
    for (int i = 0; i < 4; i++)
#pragma unroll
        for (int j = 0; j < 4; j++)
#pragma unroll
            for (int r = 0; r < 4; r++) acc[i][j][r] = 0.0f;

    load_stage(0, 0);
    load_stage(1, 1);

    // ldmatrix lane-address components
    const int arow = lane & 15;
    const int aoff = (lane >> 4) << 4;
    const int brow = ((lane & 16) >> 1) + (lane & 7);
    const int boff = (lane & 8) << 1;

    int s = 0;
    for (int ts = 0; ts < T; ts++) {
        if (ts + 1 < T) asm volatile("cp.async.wait_group 1;" ::: "memory");
        else            asm volatile("cp.async.wait_group 0;" ::: "memory");
        __syncthreads();
        if (ts + 2 < T) {
            int ns = s + 2;
            if (ns >= 3) ns -= 3;
            load_stage(ts + 2, ns);
        }

        const uint32_t saA = sb + SA_ST(s);
        const uint32_t sbB = sb + SB_ST(s);
#pragma unroll
        for (int kk = 0; kk < 4; kk++) {            // 4 x k16 steps = K64
            uint32_t af[4][4], bf[4][2];
#pragma unroll
            for (int mi = 0; mi < 4; mi++)
                ldm_x4(af[mi], saA + (wm + mi * 16 + arow) * 144 + aoff + kk * 32);
#pragma unroll
            for (int nj = 0; nj < 2; nj++) {
                uint32_t r4[4];
                ldm_x4(r4, sbB + (wn + nj * 16 + brow) * 144 + boff + kk * 32);
                bf[nj * 2][0]     = r4[0];
                bf[nj * 2][1]     = r4[1];
                bf[nj * 2 + 1][0] = r4[2];
                bf[nj * 2 + 1][1] = r4[3];
            }
#pragma unroll
            for (int mi = 0; mi < 4; mi++)
#pragma unroll
                for (int ni = 0; ni < 4; ni++)
                    mma_f16(acc[mi][ni], af[mi], bf[ni]);
        }
        if (++s == 3) s = 0;
    }

#pragma unroll
    for (int mi = 0; mi < 4; mi++) {
#pragma unroll
        for (int ni = 0; ni < 4; ni++) {
            const int gn = bn + wn + ni * 8 + t * 2;
#pragma unroll
            for (int r = 0; r < 2; r++) {
                const int gm = bm + wm + mi * 16 + g + r * 8;
                float v0 = acc[mi][ni][r * 2 + 0];
                float v1 = acc[mi][ni][r * 2 + 1];
                if (EPI != 3) {
                    v0 += bias[gn];
                    v1 += bias[gn + 1];
                }
                if (EPI == 2) {
                    v0 = gelu_f(v0);
                    v1 = gelu_f(v1);
                }
                if (EPI == 0 || EPI == 2) {         // half out, N%128==0
                    __half2 h = __floats2half2_rn(v0, v1);
                    *(__half2*)((__half*)Cv + (size_t)gm * N + gn) = h;
                } else if (EPI == 1) {              // float out + residual
                    float* C = (float*)Cv;
                    v0 += res[(size_t)gm * N + gn];
                    v1 += res[(size_t)gm * N + gn + 1];
                    C[(size_t)gm * N + gn]     = v0;
                    C[(size_t)gm * N + gn + 1] = v1;
                } else {                            // EPI 3: float out, ragged N
                    float* C = (float*)Cv;
                    if (gn < N)     C[(size_t)gm * N + gn]     = v0;
                    if (gn + 1 < N) C[(size_t)gm * N + gn + 1] = v1;
                }
            }
        }
    }
}

// ---------------------------------------------------------------------------
// 64x64-tile GEMM for narrow/wave-quantized GEMMs (proj, fc2, fc1).
//   EPI: 1 +bias+res -> float; 2 +bias+GELU -> half
// 128 threads, 4 warps 2x2, warp tile 32x32. Same k16 accumulation order as
// tc_gemm_k (bit-identical results). Grid (M/64, N/64). Up to 4 CTA/SM.
// ---------------------------------------------------------------------------
#define G64_B   (64 * 144)
#define S64A(s) ((s) * 2 * G64_B)
#define S64B(s) ((s) * 2 * G64_B + G64_B)
#define SMEM_G64 (6 * G64_B)        // 55296 B

template <int EPI>
__global__ __launch_bounds__(128, 4) void tc_gemm64_k(
    const __half* __restrict__ A, const __half* __restrict__ Bt,
    const float* __restrict__ bias, const float* __restrict__ res,
    void* __restrict__ Cv, int N, int K)
{
    extern __shared__ char smem[];
    const uint32_t sb = smem_u32(smem);
    const int tid  = threadIdx.x;
    const int lane = tid & 31;
    const int wid  = tid >> 5;
    const int wm   = (wid >> 1) * 32;
    const int wn   = (wid & 1) * 32;
    const int bm   = blockIdx.x * 64;
    const int bn   = blockIdx.y * 64;
    const int g    = lane >> 2;
    const int t    = lane & 3;
    const int T    = K >> 6;

    auto load_stage = [&](int step, int s) {
        const __half* Ap = A  + (size_t)bm * K + step * 64;
        const __half* Bp = Bt + (size_t)bn * K + step * 64;
#pragma unroll
        for (int i = 0; i < 4; i++) {   // 512 16B chunks per operand
            int f = tid + i * 128;
            int r = f >> 3, c = f & 7;
            cp16(sb + S64A(s) + r * 144 + c * 16, Ap + (size_t)r * K + c * 8);
            cp16(sb + S64B(s) + r * 144 + c * 16, Bp + (size_t)r * K + c * 8);
        }
        asm volatile("cp.async.commit_group;" ::: "memory");
    };

    float acc[2][4][4];
#pragma unroll
    for (int i = 0; i < 2; i++)
#pragma unroll
        for (int j = 0; j < 4; j++)
#pragma unroll
            for (int r = 0; r < 4; r++) acc[i][j][r] = 0.0f;

    load_stage(0, 0);
    load_stage(1, 1);

    const int arow = lane & 15;
    const int aoff = (lane >> 4) << 4;
    const int brow = ((lane & 16) >> 1) + (lane & 7);
    const int boff = (lane & 8) << 1;

    int s = 0;
    for (int ts = 0; ts < T; ts++) {
        if (ts + 1 < T) asm volatile("cp.async.wait_group 1;" ::: "memory");
        else            asm volatile("cp.async.wait_group 0;" ::: "memory");
        __syncthreads();
        if (ts + 2 < T) {
            int ns = s + 2;
            if (ns >= 3) ns -= 3;
            load_stage(ts + 2, ns);
        }

        const uint32_t saA = sb + S64A(s);
        const uint32_t sbB = sb + S64B(s);
#pragma unroll
        for (int kk = 0; kk < 4; kk++) {
            uint32_t af[2][4], bf[4][2];
#pragma unroll
            for (int mi = 0; mi < 2; mi++)
                ldm_x4(af[mi], saA + (wm + mi * 16 + arow) * 144 + aoff + kk * 32);
#pragma unroll
            for (int nj = 0; nj < 2; nj++) {
                uint32_t r4[4];
                ldm_x4(r4, sbB + (wn + nj * 16 + brow) * 144 + boff + kk * 32);
                bf[nj * 2][0]     = r4[0];
                bf[nj * 2][1]     = r4[1];
                bf[nj * 2 + 1][0] = r4[2];
                bf[nj * 2 + 1][1] = r4[3];
            }
#pragma unroll
            for (int mi = 0; mi < 2; mi++)
#pragma unroll
                for (int ni = 0; ni < 4; ni++)
                    mma_f16(acc[mi][ni], af[mi], bf[ni]);
        }
        if (++s == 3) s = 0;
    }

#pragma unroll
    for (int mi = 0; mi < 2; mi++) {
#pragma unroll
        for (int ni = 0; ni < 4; ni++) {
            const int gn = bn + wn + ni * 8 + t * 2;
#pragma unroll
            for (int r = 0; r < 2; r++) {
                const int gm = bm + wm + mi * 16 + g + r * 8;
                float v0 = acc[mi][ni][r * 2 + 0] + bias[gn];
                float v1 = acc[mi][ni][r * 2 + 1] + bias[gn + 1];
                if (EPI == 1) {
                    float* C = (float*)Cv;
                    v0 += res[(size_t)gm * N + gn];
                    v1 += res[(size_t)gm * N + gn + 1];
                    C[(size_t)gm * N + gn]     = v0;
                    C[(size_t)gm * N + gn + 1] = v1;
                } else {                            // EPI 2: GELU -> half
                    __half2 h = __floats2half2_rn(gelu_f(v0), gelu_f(v1));
                    *(__half2*)((__half*)Cv + (size_t)gm * N + gn) = h;
                }
            }
        }
    }
}

// ---------------------------------------------------------------------------
// Weight prep: transpose [K,N] -> [N,K] with fp16 conversion (layer via z)
// Tile: 64 k x 32 n. 128B-coalesced reads AND writes (half2 stores).
// ---------------------------------------------------------------------------
__global__ __launch_bounds__(256) void transpose_cvt_k(
    const float* __restrict__ in, __half* __restrict__ out,
    int Kd, int Nd, size_t in_ls, size_t out_ls)
{
    __shared__ float t[64][33];
    const float* ip = in  + blockIdx.z * in_ls;
    __half*      op = out + blockIdx.z * out_ls;
    int n0 = blockIdx.x * 32, k0 = blockIdx.y * 64;
#pragma unroll
    for (int i = 0; i < 8; i++) {
        int idx = threadIdx.x + i * 256;
        int k = idx >> 5, n = idx & 31;
        t[k][n] = ip[(size_t)(k0 + k) * Nd + n0 + n];
    }
    __syncthreads();
#pragma unroll
    for (int i = 0; i < 4; i++) {
        int idx = threadIdx.x + i * 256;
        int n = idx >> 5, kp = idx & 31;
        __half2 h = __floats2half2_rn(t[2 * kp][n], t[2 * kp + 1][n]);
        *(__half2*)&op[(size_t)(n0 + n) * Kd + k0 + 2 * kp] = h;
    }
}

// wte copy-convert: 8 elems/thread, 16B loads + 16B stores
__global__ __launch_bounds__(256) void wte_cvt_k(const float* __restrict__ wte) {
    size_t i = ((size_t)blockIdx.x * 256 + threadIdx.x) * 8;
    if (i >= (size_t)NVP * ND) return;
    int n = (int)(i / ND);                 // all 8 in same row (ND % 8 == 0)
    __half2 h[4];
    if (n < NV) {
        float4 a = *(const float4*)&wte[i];
        float4 b = *(const float4*)&wte[i + 4];
        h[0] = __floats2half2_rn(a.x, a.y);
        h[1] = __floats2half2_rn(a.z, a.w);
        h[2] = __floats2half2_rn(b.x, b.y);
        h[3] = __floats2half2_rn(b.z, b.w);
    } else {
        h[0] = h[1] = h[2] = h[3] = __floats2half2_rn(0.0f, 0.0f);
    }
    *(uint4*)&g_wteT[i] = *(uint4*)h;
}

// ---------------------------------------------------------------------------
// Embedding (fp32 residual stream)
// ---------------------------------------------------------------------------
__global__ __launch_bounds__(256) void embed_k(const int* __restrict__ idx,
                                               const float* __restrict__ wte,
                                               const float* __restrict__ pos) {
    int i = blockIdx.x * 256 + threadIdx.x;
    if (i >= NTOK * ND) return;
    int tok = i / ND;
    int d   = i - tok * ND;
    int t   = tok & (NT - 1);
    g_x[i] = wte[(size_t)idx[tok] * ND + d] + pos[t * ND + d];
}

// ---------------------------------------------------------------------------
// LayerNorm: single-pass warp-shuffle reduction; half output for fp16 mma
// ---------------------------------------------------------------------------
__global__ __launch_bounds__(256) void ln_k(const float* __restrict__ in,
                                            const float* __restrict__ gamma,
                                            const float* __restrict__ beta,
                                            __half* __restrict__ out) {
    int row = blockIdx.x;
    int tid = threadIdx.x;
    int lane = tid & 31, wid = tid >> 5;
    const float* x = in + (size_t)row * ND;
    float v0 = x[tid], v1 = x[tid + 256], v2 = x[tid + 512];

    float s  = v0 + v1 + v2;
    float sq = v0 * v0 + v1 * v1 + v2 * v2;
#pragma unroll
    for (int off = 16; off > 0; off >>= 1) {
        s  += __shfl_down_sync(0xffffffffu, s,  off);
        sq += __shfl_down_sync(0xffffffffu, sq, off);
    }
    __shared__ float ws[8], wq[8];
    if (lane == 0) { ws[wid] = s; wq[wid] = sq; }
    __syncthreads();
    float S = 0.0f, Q = 0.0f;
#pragma unroll
    for (int i = 0; i < 8; i++) { S += ws[i]; Q += wq[i]; }
    float m   = S * (1.0f / ND);
    float var = Q * (1.0f / ND) - m * m;
    float inv = rsqrtf(var + 1e-5f);

    __half* o = out + (size_t)row * ND;
    o[tid]       = __float2half_rn((v0 - m) * inv * gamma[tid]       + beta[tid]);
    o[tid + 256] = __float2half_rn((v1 - m) * inv * gamma[tid + 256] + beta[tid + 256]);
    o[tid + 512] = __float2half_rn((v2 - m) * inv * gamma[tid + 512] + beta[tid + 512]);
}

// ---------------------------------------------------------------------------
// Fused flash attention: one block per (64 q-rows, head), 128 threads =
// 4 warps x 16 q-rows. K/V double-buffered: tile tt+1's cp.async is issued
// BEFORE waiting on tile tt, hiding global latency under compute.
// Q/P via ldmatrix.x4, K x2, V x2.trans (proven R12 fragment paths).
// ---------------------------------------------------------------------------
#define FPW   36                         // pitch in words
#define FT_B  (64 * 144)                 // tile bytes
#define FLASH_SMEM (6 * FT_B)            // Q + P + 2K + 2V = 55296 B

__global__ __launch_bounds__(128) void flash_attn_k() {
    int bh = blockIdx.y;
    int b  = bh / NH;
    int h  = bh - b * NH;
    int q0 = blockIdx.x * 64;

    extern __shared__ char fsm[];
    const uint32_t sq  = smem_u32(fsm);
    const uint32_t sp  = sq + FT_B;
    const uint32_t skb = sq + 2 * FT_B;          // 2 x K buffers
    const uint32_t svb = sq + 4 * FT_B;          // 2 x V buffers
    uint32_t* PwS = (uint32_t*)(fsm + FT_B);

    const int tid  = threadIdx.x;
    const int lane = tid & 31, wid = tid >> 5;
    const int g = lane >> 2, t = lane & 3;
    const int wm = wid * 16;
    const int arow = lane & 15;
    const int aoff = (lane >> 4) << 4;
    const int krow = lane & 7;
    const int koff = (lane & 8) << 1;

    const __half* base = g_qkv + (size_t)b * NT * N3D + h * NHD;

    // Q tile (resident all iterations): 512 16B chunks
#pragma unroll
    for (int i = 0; i < 4; i++) {
        int f = tid + i * 128;
        int r = f >> 3, c = f & 7;
        cp16(sq + r * 144 + c * 16, base + (size_t)(q0 + r) * N3D + c * 8);
    }
    asm volatile("cp.async.commit_group;" ::: "memory");

    auto load_kv = [&](int k0, int sbuf) {
#pragma unroll
        for (int i = 0; i < 4; i++) {
            int f = tid + i * 128;
            int r = f >> 3, c = f & 7;
            cp16(skb + sbuf * FT_B + r * 144 + c * 16,
                 base + (size_t)(k0 + r) * N3D + ND + c * 8);
            cp16(svb + sbuf * FT_B + r * 144 + c * 16,
                 base + (size_t)(k0 + r) * N3D + 2 * ND + c * 8);
        }
        asm volatile("cp.async.commit_group;" ::: "memory");
    };
    load_kv(0, 0);

    float acc[8][4];
#pragma unroll
    for (int i = 0; i < 8; i++)
#pragma unroll
        for (int r = 0; r < 4; r++) acc[i][r] = 0.0f;
    float m[2] = {-1e30f, -1e30f};
    float l[2] = {0.0f, 0.0f};

    const int T = (q0 >> 6) + 1;

    for (int tt = 0; tt < T; tt++) {
        const int k0 = tt * 64;
        const int cb = tt & 1;
        __syncthreads();                 // other buffer's prior readers done
        if (tt + 1 < T) {
            load_kv(k0 + 64, cb ^ 1);    // issue next tile BEFORE waiting
            asm volatile("cp.async.wait_group 1;" ::: "memory");
        } else {
            asm volatile("cp.async.wait_group 0;" ::: "memory");
        }
        __syncthreads();                 // tile tt visible

        const uint32_t sk = skb + cb * FT_B;
        const uint32_t sv = svb + cb * FT_B;

        // S = Q.K^T (4 x k16 steps over 64 dims)
        float s[8][4];
#pragma unroll
        for (int i = 0; i < 8; i++)
#pragma unroll
            for (int r = 0; r < 4; r++) s[i][r] = 0.0f;
#pragma unroll
        for (int kk = 0; kk < 4; kk++) {
            uint32_t af[4];
            ldm_x4(af, sq + (wm + arow) * 144 + aoff + kk * 32);
#pragma unroll
            for (int ni = 0; ni < 8; ni++) {
                uint32_t bf[2];
                ldm_x2(bf, sk + (ni * 8 + krow) * 144 + koff + kk * 32);
                mma_f16(s[ni], af, bf);
            }
        }

        // scale + causal mask (diagonal tile only)
        const bool diag = (k0 == q0);
#pragma unroll
        for (int ni = 0; ni < 8; ni++)
#pragma unroll
            for (int r = 0; r < 2; r++)
#pragma unroll
                for (int c = 0; c < 2; c++) {
                    float v = s[ni][r * 2 + c] * 0.125f;
                    if (diag && (ni * 8 + t * 2 + c) > (wm + g + 8 * r))
                        v = -1e30f;
                    s[ni][r * 2 + c] = v;
                }

        // per-row tile max (quad reduce over t)
        float mt[2] = {-1e30f, -1e30f};
#pragma unroll
        for (int ni = 0; ni < 8; ni++)
#pragma unroll
            for (int r = 0; r < 2; r++)
                mt[r] = fmaxf(mt[r], fmaxf(s[ni][r * 2], s[ni][r * 2 + 1]));
#pragma unroll
        for (int r = 0; r < 2; r++) {
            mt[r] = fmaxf(mt[r], __shfl_xor_sync(0xffffffffu, mt[r], 1));
            mt[r] = fmaxf(mt[r], __shfl_xor_sync(0xffffffffu, mt[r], 2));
        }

        float mn[2], sc[2], ls[2] = {0.0f, 0.0f};
#pragma unroll
        for (int r = 0; r < 2; r++) {
            mn[r] = fmaxf(m[r], mt[r]);
            sc[r] = __expf(m[r] - mn[r]);
        }

        // P = exp(S - mn), fp16-rounded; write straight to smem as half2
#pragma unroll
        for (int ni = 0; ni < 8; ni++)
#pragma unroll
            for (int r = 0; r < 2; r++) {
                float p0 = __expf(s[ni][r * 2 + 0] - mn[r]);
                float p1 = __expf(s[ni][r * 2 + 1] - mn[r]);
                __half2 hh = __floats2half2_rn(p0, p1);
                ls[r] += __low2float(hh) + __high2float(hh);
                PwS[(wm + g + 8 * r) * FPW + ni * 4 + t] = *(uint32_t*)&hh;
            }
#pragma unroll
        for (int r = 0; r < 2; r++) {
            ls[r] += __shfl_xor_sync(0xffffffffu, ls[r], 1);
            ls[r] += __shfl_xor_sync(0xffffffffu, ls[r], 2);
            l[r] = l[r] * sc[r] + ls[r];
            m[r] = mn[r];
        }

        // rescale O accumulator
#pragma unroll
        for (int ni = 0; ni < 8; ni++)
#pragma unroll
            for (int r = 0; r < 2; r++) {
                acc[ni][r * 2]     *= sc[r];
                acc[ni][r * 2 + 1] *= sc[r];
            }
        __syncthreads();                 // Ps visible to all warps

        // O += P.V  (A = P via ldmatrix.x4; B = V via ldmatrix.x2.trans)
#pragma unroll
        for (int kk = 0; kk < 4; kk++) {
            uint32_t af[4];
            ldm_x4(af, sp + (wm + arow) * 144 + aoff + kk * 32);
#pragma unroll
            for (int ni = 0; ni < 8; ni++) {
                uint32_t bf0, bf1;
                uint32_t addr = sv + (kk * 16 + (lane & 15)) * 144 + ni * 16;
                asm volatile(
                    "ldmatrix.sync.aligned.m8n8.x2.trans.shared.b16 {%0,%1}, [%2];"
                    : "=r"(bf0), "=r"(bf1) : "r"(addr));
                uint32_t bf[2] = {bf0, bf1};
                mma_f16(acc[ni], af, bf);
            }
        }
    }

    // O /= l ; write half (feeds proj GEMM)
    float inv[2] = {1.0f / l[0], 1.0f / l[1]};
    __half* o = g_ao + ((size_t)b * NT + q0) * ND + h * NHD;
#pragma unroll
    for (int ni = 0; ni < 8; ni++) {
        const int cn = ni * 8 + t * 2;
#pragma unroll
        for (int r = 0; r < 2; r++) {
            const int rm = wm + g + r * 8;
            __half2 hh = __floats2half2_rn(acc[ni][r * 2 + 0] * inv[r],
                                           acc[ni][r * 2 + 1] * inv[r]);
            *(__half2*)&o[(size_t)rm * ND + cn] = hh;
        }
    }
}

// ---------------------------------------------------------------------------
// Host driver — kernel launches only (graph-capturable)
// ---------------------------------------------------------------------------
extern "C" void kernel_launch(void* const* d_in, const int* in_sizes, int n_in,
                              void* d_out, int out_size) {
    const int*   idx   = (const int*)  d_in[0];
    const float* wte   = (const float*)d_in[1];
    const float* pos   = (const float*)d_in[2];
    const float* ln1g  = (const float*)d_in[3];
    const float* ln1b  = (const float*)d_in[4];
    const float* qkvw  = (const float*)d_in[5];
    const float* qkvb  = (const float*)d_in[6];
    const float* projw = (const float*)d_in[7];
    const float* projb = (const float*)d_in[8];
    const float* ln2g  = (const float*)d_in[9];
    const float* ln2b  = (const float*)d_in[10];
    const float* fc1w  = (const float*)d_in[11];
    const float* fc1b  = (const float*)d_in[12];
    const float* fc2w  = (const float*)d_in[13];
    const float* fc2b  = (const float*)d_in[14];
    const float* lnfg  = (const float*)d_in[15];
    const float* lnfb  = (const float*)d_in[16];

    float* px;
    __half *ph, *pao, *pfc1, *pqkv;
    __half *pwteT, *pqkvT, *pprojT, *pfc1T, *pfc2T;
    cudaGetSymbolAddress((void**)&px,    g_x);
    cudaGetSymbolAddress((void**)&ph,    g_h);
    cudaGetSymbolAddress((void**)&pao,   g_ao);
    cudaGetSymbolAddress((void**)&pfc1,  g_fc1);
    cudaGetSymbolAddress((void**)&pqkv,  g_qkv);
    cudaGetSymbolAddress((void**)&pwteT, g_wteT);
    cudaGetSymbolAddress((void**)&pqkvT, g_qkvT);
    cudaGetSymbolAddress((void**)&pprojT,g_projT);
    cudaGetSymbolAddress((void**)&pfc1T, g_fc1T);
    cudaGetSymbolAddress((void**)&pfc2T, g_fc2T);

    cudaFuncSetAttribute(tc_gemm_k<0>, cudaFuncAttributeMaxDynamicSharedMemorySize, SMEM_GEMM);
    cudaFuncSetAttribute(tc_gemm_k<1>, cudaFuncAttributeMaxDynamicSharedMemorySize, SMEM_GEMM);
    cudaFuncSetAttribute(tc_gemm_k<2>, cudaFuncAttributeMaxDynamicSharedMemorySize, SMEM_GEMM);
    cudaFuncSetAttribute(tc_gemm_k<3>, cudaFuncAttributeMaxDynamicSharedMemorySize, SMEM_GEMM);
    cudaFuncSetAttribute(tc_gemm64_k<1>, cudaFuncAttributeMaxDynamicSharedMemorySize, SMEM_G64);
    cudaFuncSetAttribute(tc_gemm64_k<2>, cudaFuncAttributeMaxDynamicSharedMemorySize, SMEM_G64);
    cudaFuncSetAttribute(flash_attn_k, cudaFuncAttributeMaxDynamicSharedMemorySize, FLASH_SMEM);

    // ---- weight prep (every replay; deterministic) ----
    wte_cvt_k<<<(int)(((size_t)NVP * ND / 8 + 255) / 256), 256>>>(wte);
    transpose_cvt_k<<<dim3(N3D / 32, ND / 64, NL), 256>>>(
        qkvw, pqkvT, ND, N3D, (size_t)ND * N3D, (size_t)N3D * ND);
    transpose_cvt_k<<<dim3(ND / 32, ND / 64, NL), 256>>>(
        projw, pprojT, ND, ND, (size_t)ND * ND, (size_t)ND * ND);
    transpose_cvt_k<<<dim3(N4D / 32, ND / 64, NL), 256>>>(
        fc1w, pfc1T, ND, N4D, (size_t)ND * N4D, (size_t)N4D * ND);
    transpose_cvt_k<<<dim3(ND / 32, N4D / 64, NL), 256>>>(
        fc2w, pfc2T, N4D, ND, (size_t)N4D * ND, (size_t)ND * N4D);

    embed_k<<<(NTOK * ND + 255) / 256, 256>>>(idx, wte, pos);

    for (int l = 0; l < NL; l++) {
        // --- attention half ---
        ln_k<<<NTOK, 256>>>(px, ln1g + (size_t)l * ND, ln1b + (size_t)l * ND, ph);

        tc_gemm_k<0><<<dim3(NTOK / 128, N3D / 128), 256, SMEM_GEMM>>>(
            ph, pqkvT + (size_t)l * N3D * ND, qkvb + (size_t)l * N3D,
            nullptr, pqkv, N3D, ND);

        flash_attn_k<<<dim3(NT / 64, NB * NH), 128, FLASH_SMEM>>>();

        tc_gemm64_k<1><<<dim3(NTOK / 64, ND / 64), 128, SMEM_G64>>>(
            pao, pprojT + (size_t)l * ND * ND, projb + (size_t)l * ND,
            px, px, ND, ND);

        // --- MLP half ---
        ln_k<<<NTOK, 256>>>(px, ln2g + (size_t)l * ND, ln2b + (size_t)l * ND, ph);

        tc_gemm64_k<2><<<dim3(NTOK / 64, N4D / 64), 128, SMEM_G64>>>(
            ph, pfc1T + (size_t)l * N4D * ND, fc1b + (size_t)l * N4D,
            nullptr, pfc1, N4D, ND);

        tc_gemm64_k<1><<<dim3(NTOK / 64, ND / 64), 128, SMEM_G64>>>(
            pfc1, pfc2T + (size_t)l * ND * N4D, fc2b + (size_t)l * ND,
            px, px, ND, N4D);
    }

    // final LN + tied head
    ln_k<<<NTOK, 256>>>(px, lnfg, lnfb, ph);
    tc_gemm_k<3><<<dim3(NTOK / 128, NVP / 128), 256, SMEM_GEMM>>>(
        ph, pwteT, nullptr, nullptr, (float*)d_out, NV, ND);
}

// round 17
// speedup vs baseline: 1.1050x; 1.0010x over previous
#include <cuda_runtime.h>
#include <cuda_fp16.h>
#include <math.h>
#include <stdint.h>

// GPT-2 small config (fixed by the problem)
#define NB   2
#define NT   1024
#define ND   768
#define NH   12
#define NL   12
#define NV   50257
#define NVP  50304                // NV padded to multiple of 128
#define NHD  64
#define NTOK (NB * NT)            // 2048 token rows
#define N3D  (3 * ND)             // 2304
#define N4D  (4 * ND)             // 3072

// ---------------------------------------------------------------------------
// Scratch (device globals; allocation inside kernel_launch is forbidden)
// ---------------------------------------------------------------------------
__device__ float g_x [NTOK * ND];                       // fp32 residual stream
__device__ __align__(16) __half g_h  [NTOK * ND];       // LN out
__device__ __align__(16) __half g_qkv[NTOK * N3D];
__device__ __align__(16) __half g_ao [NTOK * ND];       // attn out
__device__ __align__(16) __half g_fc1[NTOK * N4D];      // GELU out

// fp16 weights, transposed to [N,K] so GEMM B-operand is K-major like A
__device__ __align__(16) __half g_wteT [(size_t)NVP * ND];   // rows >= NV zeroed
__device__ __align__(16) __half g_qkvT [(size_t)NL * N3D * ND];
__device__ __align__(16) __half g_projT[(size_t)NL * ND * ND];
__device__ __align__(16) __half g_fc1T [(size_t)NL * N4D * ND];
__device__ __align__(16) __half g_fc2T [(size_t)NL * ND * N4D];

// ---------------------------------------------------------------------------
// Helpers
// ---------------------------------------------------------------------------
__device__ __forceinline__ uint32_t smem_u32(const void* p) {
    uint32_t a;
    asm("{ .reg .u64 t; cvta.to.shared.u64 t, %1; cvt.u32.u64 %0, t; }"
        : "=r"(a) : "l"(p));
    return a;
}
__device__ __forceinline__ void cp16(uint32_t dst, const void* src) {
    asm volatile("cp.async.cg.shared.global [%0], [%1], 16;"
                 :: "r"(dst), "l"(src) : "memory");
}
// fp16 mma, fp32 accumulate: D[16,8] += A[16,16] * B[16,8]
__device__ __forceinline__ void mma_f16(float* c, const uint32_t* a,
                                        const uint32_t* b) {
    asm volatile(
        "mma.sync.aligned.m16n8k16.row.col.f32.f16.f16.f32 "
        "{%0,%1,%2,%3}, {%4,%5,%6,%7}, {%8,%9}, {%0,%1,%2,%3};"
        : "+f"(c[0]), "+f"(c[1]), "+f"(c[2]), "+f"(c[3])
        : "r"(a[0]), "r"(a[1]), "r"(a[2]), "r"(a[3]), "r"(b[0]), "r"(b[1]));
}
__device__ __forceinline__ void ldm_x4(uint32_t* r, uint32_t addr) {
    asm volatile("ldmatrix.sync.aligned.m8n8.x4.shared.b16 {%0,%1,%2,%3}, [%4];"
                 : "=r"(r[0]), "=r"(r[1]), "=r"(r[2]), "=r"(r[3]) : "r"(addr));
}
__device__ __forceinline__ void ldm_x2(uint32_t* r, uint32_t addr) {
    asm volatile("ldmatrix.sync.aligned.m8n8.x2.shared.b16 {%0,%1}, [%2];"
                 : "=r"(r[0]), "=r"(r[1]) : "r"(addr));
}
__device__ __forceinline__ float gelu_f(float v) {
    return 0.5f * v * (1.0f + erff(v * 0.70710678118654752f));
}

// GEMM smem: 3 stages x (A tile + B tile); tile = 128 rows x 72 halfs (144B)
#define GTILE_B  (128 * 144)
#define SA_ST(s) ((s) * 2 * GTILE_B)
#define SB_ST(s) ((s) * 2 * GTILE_B + GTILE_B)
#define SMEM_GEMM (6 * GTILE_B)     // 110592 B (2 CTA/SM = 216KB)

// ---------------------------------------------------------------------------
// fp16 mma GEMM (128x128 tile): C[M,N] = A[M,K] @ W (Bt = W^T as [N,K] half)
//   EPI: 0 +bias -> half (qkv); 1 +bias+res -> float; 2 +bias+GELU -> half;
//        3 none -> float (logits)
// Grid (M/128, ceil(N/128)), 256 threads. K%64==0, K/64>=2, M%128==0.
// ---------------------------------------------------------------------------
template <int EPI>
__global__ __launch_bounds__(256, 2) void tc_gemm_k(
    const __half* __restrict__ A, const __half* __restrict__ Bt,
    const float* __restrict__ bias, const float* __restrict__ res,
    void* __restrict__ Cv, int N, int K)
{
    extern __shared__ char smem[];
    const uint32_t sb = smem_u32(smem);
    const int tid  = threadIdx.x;
    const int lane = tid & 31;
    const int wid  = tid >> 5;
    const int wm   = (wid >> 2) * 64;
    const int wn   = (wid & 3) * 32;
    const int bm   = blockIdx.x * 128;
    const int bn   = blockIdx.y * 128;
    const int g    = lane >> 2;
    const int t    = lane & 3;
    const int T    = K >> 6;            // BK = 64 halfs

    auto load_stage = [&](int step, int s) {
        const __half* Ap = A  + (size_t)bm * K + step * 64;
        const __half* Bp = Bt + (size_t)bn * K + step * 64;
#pragma unroll
        for (int i = 0; i < 4; i++) {   // 1024 16B chunks per operand
            int f = tid + i * 256;
            int r = f >> 3, c = f & 7;
            cp16(sb + SA_ST(s) + r * 144 + c * 16, Ap + (size_t)r * K + c * 8);
            cp16(sb + SB_ST(s) + r * 144 + c * 16, Bp + (size_t)r * K + c * 8);
        }
        asm volatile("cp.async.commit_group;" ::: "memory");
    };

    float acc[4][4][4];
#pragma unroll
    for (int i = 0; i < 4; i++)
#pragma unroll
        for (int j = 0; j < 4; j++)
#pragma unroll
            for (int r = 0; r < 4; r++) acc[i][j][r] = 0.0f;

    load_stage(0, 0);
    load_stage(1, 1);

    // ldmatrix lane-address components
    const int arow = lane & 15;
    const int aoff = (lane >> 4) << 4;
    const int brow = ((lane & 16) >> 1) + (lane & 7);
    const int boff = (lane & 8) << 1;

    int s = 0;
    for (int ts = 0; ts < T; ts++) {
        if (ts + 1 < T) asm volatile("cp.async.wait_group 1;" ::: "memory");
        else            asm volatile("cp.async.wait_group 0;" ::: "memory");
        __syncthreads();
        if (ts + 2 < T) {
            int ns = s + 2;
            if (ns >= 3) ns -= 3;
            load_stage(ts + 2, ns);
        }

        const uint32_t saA = sb + SA_ST(s);
        const uint32_t sbB = sb + SB_ST(s);
#pragma unroll
        for (int kk = 0; kk < 4; kk++) {            // 4 x k16 steps = K64
            uint32_t af[4][4], bf[4][2];
#pragma unroll
            for (int mi = 0; mi < 4; mi++)
                ldm_x4(af[mi], saA + (wm + mi * 16 + arow) * 144 + aoff + kk * 32);
#pragma unroll
            for (int nj = 0; nj < 2; nj++) {
                uint32_t r4[4];
                ldm_x4(r4, sbB + (wn + nj * 16 + brow) * 144 + boff + kk * 32);
                bf[nj * 2][0]     = r4[0];
                bf[nj * 2][1]     = r4[1];
                bf[nj * 2 + 1][0] = r4[2];
                bf[nj * 2 + 1][1] = r4[3];
            }
#pragma unroll
            for (int mi = 0; mi < 4; mi++)
#pragma unroll
                for (int ni = 0; ni < 4; ni++)
                    mma_f16(acc[mi][ni], af[mi], bf[ni]);
        }
        if (++s == 3) s = 0;
    }

#pragma unroll
    for (int mi = 0; mi < 4; mi++) {
#pragma unroll
        for (int ni = 0; ni < 4; ni++) {
            const int gn = bn + wn + ni * 8 + t * 2;
#pragma unroll
            for (int r = 0; r < 2; r++) {
                const int gm = bm + wm + mi * 16 + g + r * 8;
                float v0 = acc[mi][ni][r * 2 + 0];
                float v1 = acc[mi][ni][r * 2 + 1];
                if (EPI != 3) {
                    v0 += bias[gn];
                    v1 += bias[gn + 1];
                }
                if (EPI == 2) {
                    v0 = gelu_f(v0);
                    v1 = gelu_f(v1);
                }
                if (EPI == 0 || EPI == 2) {         // half out, N%128==0
                    __half2 h = __floats2half2_rn(v0, v1);
                    *(__half2*)((__half*)Cv + (size_t)gm * N + gn) = h;
                } else if (EPI == 1) {              // float out + residual
                    float* C = (float*)Cv;
                    v0 += res[(size_t)gm * N + gn];
                    v1 += res[(size_t)gm * N + gn + 1];
                    C[(size_t)gm * N + gn]     = v0;
                    C[(size_t)gm * N + gn + 1] = v1;
                } else {                            // EPI 3: float out, ragged N
                    float* C = (float*)Cv;
                    if (gn < N)     C[(size_t)gm * N + gn]     = v0;
                    if (gn + 1 < N) C[(size_t)gm * N + gn + 1] = v1;
                }
            }
        }
    }
}

// ---------------------------------------------------------------------------
// 64x64-tile GEMM for narrow/wave-quantized GEMMs (proj, fc2, fc1).
//   EPI: 1 +bias+res -> float; 2 +bias+GELU -> half
// 128 threads, 4 warps 2x2, warp tile 32x32. Same k16 accumulation order as
// tc_gemm_k (bit-identical results). Grid (M/64, N/64). Up to 4 CTA/SM.
// ---------------------------------------------------------------------------
#define G64_B   (64 * 144)
#define S64A(s) ((s) * 2 * G64_B)
#define S64B(s) ((s) * 2 * G64_B + G64_B)
#define SMEM_G64 (6 * G64_B)        // 55296 B

template <int EPI>
__global__ __launch_bounds__(128, 4) void tc_gemm64_k(
    const __half* __restrict__ A, const __half* __restrict__ Bt,
    const float* __restrict__ bias, const float* __restrict__ res,
    void* __restrict__ Cv, int N, int K)
{
    extern __shared__ char smem[];
    const uint32_t sb = smem_u32(smem);
    const int tid  = threadIdx.x;
    const int lane = tid & 31;
    const int wid  = tid >> 5;
    const int wm   = (wid >> 1) * 32;
    const int wn   = (wid & 1) * 32;
    const int bm   = blockIdx.x * 64;
    const int bn   = blockIdx.y * 64;
    const int g    = lane >> 2;
    const int t    = lane & 3;
    const int T    = K >> 6;

    auto load_stage = [&](int step, int s) {
        const __half* Ap = A  + (size_t)bm * K + step * 64;
        const __half* Bp = Bt + (size_t)bn * K + step * 64;
#pragma unroll
        for (int i = 0; i < 4; i++) {   // 512 16B chunks per operand
            int f = tid + i * 128;
            int r = f >> 3, c = f & 7;
            cp16(sb + S64A(s) + r * 144 + c * 16, Ap + (size_t)r * K + c * 8);
            cp16(sb + S64B(s) + r * 144 + c * 16, Bp + (size_t)r * K + c * 8);
        }
        asm volatile("cp.async.commit_group;" ::: "memory");
    };

    float acc[2][4][4];
#pragma unroll
    for (int i = 0; i < 2; i++)
#pragma unroll
        for (int j = 0; j < 4; j++)
#pragma unroll
            for (int r = 0; r < 4; r++) acc[i][j][r] = 0.0f;

    load_stage(0, 0);
    load_stage(1, 1);

    const int arow = lane & 15;
    const int aoff = (lane >> 4) << 4;
    const int brow = ((lane & 16) >> 1) + (lane & 7);
    const int boff = (lane & 8) << 1;

    int s = 0;
    for (int ts = 0; ts < T; ts++) {
        if (ts + 1 < T) asm volatile("cp.async.wait_group 1;" ::: "memory");
        else            asm volatile("cp.async.wait_group 0;" ::: "memory");
        __syncthreads();
        if (ts + 2 < T) {
            int ns = s + 2;
            if (ns >= 3) ns -= 3;
            load_stage(ts + 2, ns);
        }

        const uint32_t saA = sb + S64A(s);
        const uint32_t sbB = sb + S64B(s);
#pragma unroll
        for (int kk = 0; kk < 4; kk++) {
            uint32_t af[2][4], bf[4][2];
#pragma unroll
            for (int mi = 0; mi < 2; mi++)
                ldm_x4(af[mi], saA + (wm + mi * 16 + arow) * 144 + aoff + kk * 32);
#pragma unroll
            for (int nj = 0; nj < 2; nj++) {
                uint32_t r4[4];
                ldm_x4(r4, sbB + (wn + nj * 16 + brow) * 144 + boff + kk * 32);
                bf[nj * 2][0]     = r4[0];
                bf[nj * 2][1]     = r4[1];
                bf[nj * 2 + 1][0] = r4[2];
                bf[nj * 2 + 1][1] = r4[3];
            }
#pragma unroll
            for (int mi = 0; mi < 2; mi++)
#pragma unroll
                for (int ni = 0; ni < 4; ni++)
                    mma_f16(acc[mi][ni], af[mi], bf[ni]);
        }
        if (++s == 3) s = 0;
    }

#pragma unroll
    for (int mi = 0; mi < 2; mi++) {
#pragma unroll
        for (int ni = 0; ni < 4; ni++) {
            const int gn = bn + wn + ni * 8 + t * 2;
#pragma unroll
            for (int r = 0; r < 2; r++) {
                const int gm = bm + wm + mi * 16 + g + r * 8;
                float v0 = acc[mi][ni][r * 2 + 0] + bias[gn];
                float v1 = acc[mi][ni][r * 2 + 1] + bias[gn + 1];
                if (EPI == 1) {
                    float* C = (float*)Cv;
                    v0 += res[(size_t)gm * N + gn];
                    v1 += res[(size_t)gm * N + gn + 1];
                    C[(size_t)gm * N + gn]     = v0;
                    C[(size_t)gm * N + gn + 1] = v1;
                } else {                            // EPI 2: GELU -> half
                    __half2 h = __floats2half2_rn(gelu_f(v0), gelu_f(v1));
                    *(__half2*)((__half*)Cv + (size_t)gm * N + gn) = h;
                }
            }
        }
    }
}

// ---------------------------------------------------------------------------
// Weight prep: transpose [K,N] -> [N,K] with fp16 conversion (layer via z)
// Tile: 64 k x 32 n. 128B-coalesced reads AND writes (half2 stores).
// ---------------------------------------------------------------------------
__global__ __launch_bounds__(256) void transpose_cvt_k(
    const float* __restrict__ in, __half* __restrict__ out,
    int Kd, int Nd, size_t in_ls, size_t out_ls)
{
    __shared__ float t[64][33];
    const float* ip = in  + blockIdx.z * in_ls;
    __half*      op = out + blockIdx.z * out_ls;
    int n0 = blockIdx.x * 32, k0 = blockIdx.y * 64;
#pragma unroll
    for (int i = 0; i < 8; i++) {
        int idx = threadIdx.x + i * 256;
        int k = idx >> 5, n = idx & 31;
        t[k][n] = ip[(size_t)(k0 + k) * Nd + n0 + n];
    }
    __syncthreads();
#pragma unroll
    for (int i = 0; i < 4; i++) {
        int idx = threadIdx.x + i * 256;
        int n = idx >> 5, kp = idx & 31;
        __half2 h = __floats2half2_rn(t[2 * kp][n], t[2 * kp + 1][n]);
        *(__half2*)&op[(size_t)(n0 + n) * Kd + k0 + 2 * kp] = h;
    }
}

// wte copy-convert: 8 elems/thread, 16B loads + 16B stores
__global__ __launch_bounds__(256) void wte_cvt_k(const float* __restrict__ wte) {
    size_t i = ((size_t)blockIdx.x * 256 + threadIdx.x) * 8;
    if (i >= (size_t)NVP * ND) return;
    int n = (int)(i / ND);                 // all 8 in same row (ND % 8 == 0)
    __half2 h[4];
    if (n < NV) {
        float4 a = *(const float4*)&wte[i];
        float4 b = *(const float4*)&wte[i + 4];
        h[0] = __floats2half2_rn(a.x, a.y);
        h[1] = __floats2half2_rn(a.z, a.w);
        h[2] = __floats2half2_rn(b.x, b.y);
        h[3] = __floats2half2_rn(b.z, b.w);
    } else {
        h[0] = h[1] = h[2] = h[3] = __floats2half2_rn(0.0f, 0.0f);
    }
    *(uint4*)&g_wteT[i] = *(uint4*)h;
}

// ---------------------------------------------------------------------------
// Embedding (fp32 residual stream)
// ---------------------------------------------------------------------------
__global__ __launch_bounds__(256) void embed_k(const int* __restrict__ idx,
                                               const float* __restrict__ wte,
                                               const float* __restrict__ pos) {
    int i = blockIdx.x * 256 + threadIdx.x;
    if (i >= NTOK * ND) return;
    int tok = i / ND;
    int d   = i - tok * ND;
    int t   = tok & (NT - 1);
    g_x[i] = wte[(size_t)idx[tok] * ND + d] + pos[t * ND + d];
}

// ---------------------------------------------------------------------------
// LayerNorm: warp-per-row. 8 rows per 256-thread block, float4 loads,
// pure shuffle reductions — no smem, no __syncthreads. Half output.
// ---------------------------------------------------------------------------
__global__ __launch_bounds__(256) void ln_k(const float* __restrict__ in,
                                            const float* __restrict__ gamma,
                                            const float* __restrict__ beta,
                                            __half* __restrict__ out) {
    const int row  = (blockIdx.x << 3) + (threadIdx.x >> 5);
    const int lane = threadIdx.x & 31;

    const float4* x4 = (const float4*)(in + (size_t)row * ND);
    float4 v[6];
    float s = 0.0f, sq = 0.0f;
#pragma unroll
    for (int j = 0; j < 6; j++) {
        v[j] = x4[lane + 32 * j];
        s  += v[j].x + v[j].y + v[j].z + v[j].w;
        sq += v[j].x * v[j].x + v[j].y * v[j].y
            + v[j].z * v[j].z + v[j].w * v[j].w;
    }
#pragma unroll
    for (int off = 16; off > 0; off >>= 1) {
        s  += __shfl_xor_sync(0xffffffffu, s,  off);
        sq += __shfl_xor_sync(0xffffffffu, sq, off);
    }
    const float m   = s * (1.0f / ND);
    const float var = sq * (1.0f / ND) - m * m;
    const float inv = rsqrtf(var + 1e-5f);

    const float4* g4 = (const float4*)gamma;
    const float4* b4 = (const float4*)beta;
    __half* o = out + (size_t)row * ND;
#pragma unroll
    for (int j = 0; j < 6; j++) {
        const int e = lane + 32 * j;
        float4 gv = g4[e];
        float4 bv = b4[e];
        __half2 h0 = __floats2half2_rn((v[j].x - m) * inv * gv.x + bv.x,
                                       (v[j].y - m) * inv * gv.y + bv.y);
        __half2 h1 = __floats2half2_rn((v[j].z - m) * inv * gv.z + bv.z,
                                       (v[j].w - m) * inv * gv.w + bv.w);
        uint2 u;
        u.x = *(uint32_t*)&h0;
        u.y = *(uint32_t*)&h1;
        *(uint2*)&o[e * 4] = u;
    }
}

// ---------------------------------------------------------------------------
// Fused flash attention: one block per (64 q-rows, head), 128 threads =
// 4 warps x 16 q-rows. K/V double-buffered: tile tt+1's cp.async is issued
// BEFORE waiting on tile tt, hiding global latency under compute.
// Q/P via ldmatrix.x4, K x2, V x2.trans (proven R12 fragment paths).
// ---------------------------------------------------------------------------
#define FPW   36                         // pitch in words
#define FT_B  (64 * 144)                 // tile bytes
#define FLASH_SMEM (6 * FT_B)            // Q + P + 2K + 2V = 55296 B

__global__ __launch_bounds__(128) void flash_attn_k() {
    int bh = blockIdx.y;
    int b  = bh / NH;
    int h  = bh - b * NH;
    int q0 = blockIdx.x * 64;

    extern __shared__ char fsm[];
    const uint32_t sq  = smem_u32(fsm);
    const uint32_t sp  = sq + FT_B;
    const uint32_t skb = sq + 2 * FT_B;          // 2 x K buffers
    const uint32_t svb = sq + 4 * FT_B;          // 2 x V buffers
    uint32_t* PwS = (uint32_t*)(fsm + FT_B);

    const int tid  = threadIdx.x;
    const int lane = tid & 31, wid = tid >> 5;
    const int g = lane >> 2, t = lane & 3;
    const int wm = wid * 16;
    const int arow = lane & 15;
    const int aoff = (lane >> 4) << 4;
    const int krow = lane & 7;
    const int koff = (lane & 8) << 1;

    const __half* base = g_qkv + (size_t)b * NT * N3D + h * NHD;

    // Q tile (resident all iterations): 512 16B chunks
#pragma unroll
    for (int i = 0; i < 4; i++) {
        int f = tid + i * 128;
        int r = f >> 3, c = f & 7;
        cp16(sq + r * 144 + c * 16, base + (size_t)(q0 + r) * N3D + c * 8);
    }
    asm volatile("cp.async.commit_group;" ::: "memory");

    auto load_kv = [&](int k0, int sbuf) {
#pragma unroll
        for (int i = 0; i < 4; i++) {
            int f = tid + i * 128;
            int r = f >> 3, c = f & 7;
            cp16(skb + sbuf * FT_B + r * 144 + c * 16,
                 base + (size_t)(k0 + r) * N3D + ND + c * 8);
            cp16(svb + sbuf * FT_B + r * 144 + c * 16,
                 base + (size_t)(k0 + r) * N3D + 2 * ND + c * 8);
        }
        asm volatile("cp.async.commit_group;" ::: "memory");
    };
    load_kv(0, 0);

    float acc[8][4];
#pragma unroll
    for (int i = 0; i < 8; i++)
#pragma unroll
        for (int r = 0; r < 4; r++) acc[i][r] = 0.0f;
    float m[2] = {-1e30f, -1e30f};
    float l[2] = {0.0f, 0.0f};

    const int T = (q0 >> 6) + 1;

    for (int tt = 0; tt < T; tt++) {
        const int k0 = tt * 64;
        const int cb = tt & 1;
        __syncthreads();                 // other buffer's prior readers done
        if (tt + 1 < T) {
            load_kv(k0 + 64, cb ^ 1);    // issue next tile BEFORE waiting
            asm volatile("cp.async.wait_group 1;" ::: "memory");
        } else {
            asm volatile("cp.async.wait_group 0;" ::: "memory");
        }
        __syncthreads();                 // tile tt visible

        const uint32_t sk = skb + cb * FT_B;
        const uint32_t sv = svb + cb * FT_B;

        // S = Q.K^T (4 x k16 steps over 64 dims)
        float s[8][4];
#pragma unroll
        for (int i = 0; i < 8; i++)
#pragma unroll
            for (int r = 0; r < 4; r++) s[i][r] = 0.0f;
#pragma unroll
        for (int kk = 0; kk < 4; kk++) {
            uint32_t af[4];
            ldm_x4(af, sq + (wm + arow) * 144 + aoff + kk * 32);
#pragma unroll
            for (int ni = 0; ni < 8; ni++) {
                uint32_t bf[2];
                ldm_x2(bf, sk + (ni * 8 + krow) * 144 + koff + kk * 32);
                mma_f16(s[ni], af, bf);
            }
        }

        // scale + causal mask (diagonal tile only)
        const bool diag = (k0 == q0);
#pragma unroll
        for (int ni = 0; ni < 8; ni++)
#pragma unroll
            for (int r = 0; r < 2; r++)
#pragma unroll
                for (int c = 0; c < 2; c++) {
                    float v = s[ni][r * 2 + c] * 0.125f;
                    if (diag && (ni * 8 + t * 2 + c) > (wm + g + 8 * r))
                        v = -1e30f;
                    s[ni][r * 2 + c] = v;
                }

        // per-row tile max (quad reduce over t)
        float mt[2] = {-1e30f, -1e30f};
#pragma unroll
        for (int ni = 0; ni < 8; ni++)
#pragma unroll
            for (int r = 0; r < 2; r++)
                mt[r] = fmaxf(mt[r], fmaxf(s[ni][r * 2], s[ni][r * 2 + 1]));
#pragma unroll
        for (int r = 0; r < 2; r++) {
            mt[r] = fmaxf(mt[r], __shfl_xor_sync(0xffffffffu, mt[r], 1));
            mt[r] = fmaxf(mt[r], __shfl_xor_sync(0xffffffffu, mt[r], 2));
        }

        float mn[2], sc[2], ls[2] = {0.0f, 0.0f};
#pragma unroll
        for (int r = 0; r < 2; r++) {
            mn[r] = fmaxf(m[r], mt[r]);
            sc[r] = __expf(m[r] - mn[r]);
        }

        // P = exp(S - mn), fp16-rounded; write straight to smem as half2
#pragma unroll
        for (int ni = 0; ni < 8; ni++)
#pragma unroll
            for (int r = 0; r < 2; r++) {
                float p0 = __expf(s[ni][r * 2 + 0] - mn[r]);
                float p1 = __expf(s[ni][r * 2 + 1] - mn[r]);
                __half2 hh = __floats2half2_rn(p0, p1);
                ls[r] += __low2float(hh) + __high2float(hh);
                PwS[(wm + g + 8 * r) * FPW + ni * 4 + t] = *(uint32_t*)&hh;
            }
#pragma unroll
        for (int r = 0; r < 2; r++) {
            ls[r] += __shfl_xor_sync(0xffffffffu, ls[r], 1);
            ls[r] += __shfl_xor_sync(0xffffffffu, ls[r], 2);
            l[r] = l[r] * sc[r] + ls[r];
            m[r] = mn[r];
        }

        // rescale O accumulator
#pragma unroll
        for (int ni = 0; ni < 8; ni++)
#pragma unroll
            for (int r = 0; r < 2; r++) {
                acc[ni][r * 2]     *= sc[r];
                acc[ni][r * 2 + 1] *= sc[r];
            }
        __syncthreads();                 // Ps visible to all warps

        // O += P.V  (A = P via ldmatrix.x4; B = V via ldmatrix.x2.trans)
#pragma unroll
        for (int kk = 0; kk < 4; kk++) {
            uint32_t af[4];
            ldm_x4(af, sp + (wm + arow) * 144 + aoff + kk * 32);
#pragma unroll
            for (int ni = 0; ni < 8; ni++) {
                uint32_t bf0, bf1;
                uint32_t addr = sv + (kk * 16 + (lane & 15)) * 144 + ni * 16;
                asm volatile(
                    "ldmatrix.sync.aligned.m8n8.x2.trans.shared.b16 {%0,%1}, [%2];"
                    : "=r"(bf0), "=r"(bf1) : "r"(addr));
                uint32_t bf[2] = {bf0, bf1};
                mma_f16(acc[ni], af, bf);
            }
        }
    }

    // O /= l ; write half (feeds proj GEMM)
    float inv[2] = {1.0f / l[0], 1.0f / l[1]};
    __half* o = g_ao + ((size_t)b * NT + q0) * ND + h * NHD;
#pragma unroll
    for (int ni = 0; ni < 8; ni++) {
        const int cn = ni * 8 + t * 2;
#pragma unroll
        for (int r = 0; r < 2; r++) {
            const int rm = wm + g + r * 8;
            __half2 hh = __floats2half2_rn(acc[ni][r * 2 + 0] * inv[r],
                                           acc[ni][r * 2 + 1] * inv[r]);
            *(__half2*)&o[(size_t)rm * ND + cn] = hh;
        }
    }
}

// ---------------------------------------------------------------------------
// Host driver — kernel launches only (graph-capturable)
// ---------------------------------------------------------------------------
extern "C" void kernel_launch(void* const* d_in, const int* in_sizes, int n_in,
                              void* d_out, int out_size) {
    const int*   idx   = (const int*)  d_in[0];
    const float* wte   = (const float*)d_in[1];
    const float* pos   = (const float*)d_in[2];
    const float* ln1g  = (const float*)d_in[3];
    const float* ln1b  = (const float*)d_in[4];
    const float* qkvw  = (const float*)d_in[5];
    const float* qkvb  = (const float*)d_in[6];
    const float* projw = (const float*)d_in[7];
    const float* projb = (const float*)d_in[8];
    const float* ln2g  = (const float*)d_in[9];
    const float* ln2b  = (const float*)d_in[10];
    const float* fc1w  = (const float*)d_in[11];
    const float* fc1b  = (const float*)d_in[12];
    const float* fc2w  = (const float*)d_in[13];
    const float* fc2b  = (const float*)d_in[14];
    const float* lnfg  = (const float*)d_in[15];
    const float* lnfb  = (const float*)d_in[16];

    float* px;
    __half *ph, *pao, *pfc1, *pqkv;
    __half *pwteT, *pqkvT, *pprojT, *pfc1T, *pfc2T;
    cudaGetSymbolAddress((void**)&px,    g_x);
    cudaGetSymbolAddress((void**)&ph,    g_h);
    cudaGetSymbolAddress((void**)&pao,   g_ao);
    cudaGetSymbolAddress((void**)&pfc1,  g_fc1);
    cudaGetSymbolAddress((void**)&pqkv,  g_qkv);
    cudaGetSymbolAddress((void**)&pwteT, g_wteT);
    cudaGetSymbolAddress((void**)&pqkvT, g_qkvT);
    cudaGetSymbolAddress((void**)&pprojT,g_projT);
    cudaGetSymbolAddress((void**)&pfc1T, g_fc1T);
    cudaGetSymbolAddress((void**)&pfc2T, g_fc2T);

    cudaFuncSetAttribute(tc_gemm_k<0>, cudaFuncAttributeMaxDynamicSharedMemorySize, SMEM_GEMM);
    cudaFuncSetAttribute(tc_gemm_k<1>, cudaFuncAttributeMaxDynamicSharedMemorySize, SMEM_GEMM);
    cudaFuncSetAttribute(tc_gemm_k<2>, cudaFuncAttributeMaxDynamicSharedMemorySize, SMEM_GEMM);
    cudaFuncSetAttribute(tc_gemm_k<3>, cudaFuncAttributeMaxDynamicSharedMemorySize, SMEM_GEMM);
    cudaFuncSetAttribute(tc_gemm64_k<1>, cudaFuncAttributeMaxDynamicSharedMemorySize, SMEM_G64);
    cudaFuncSetAttribute(tc_gemm64_k<2>, cudaFuncAttributeMaxDynamicSharedMemorySize, SMEM_G64);
    cudaFuncSetAttribute(flash_attn_k, cudaFuncAttributeMaxDynamicSharedMemorySize, FLASH_SMEM);

    // ---- weight prep (every replay; deterministic) ----
    wte_cvt_k<<<(int)(((size_t)NVP * ND / 8 + 255) / 256), 256>>>(wte);
    transpose_cvt_k<<<dim3(N3D / 32, ND / 64, NL), 256>>>(
        qkvw, pqkvT, ND, N3D, (size_t)ND * N3D, (size_t)N3D * ND);
    transpose_cvt_k<<<dim3(ND / 32, ND / 64, NL), 256>>>(
        projw, pprojT, ND, ND, (size_t)ND * ND, (size_t)ND * ND);
    transpose_cvt_k<<<dim3(N4D / 32, ND / 64, NL), 256>>>(
        fc1w, pfc1T, ND, N4D, (size_t)ND * N4D, (size_t)N4D * ND);
    transpose_cvt_k<<<dim3(ND / 32, N4D / 64, NL), 256>>>(
        fc2w, pfc2T, N4D, ND, (size_t)N4D * ND, (size_t)ND * N4D);

    embed_k<<<(NTOK * ND + 255) / 256, 256>>>(idx, wte, pos);

    for (int l = 0; l < NL; l++) {
        // --- attention half ---
        ln_k<<<NTOK / 8, 256>>>(px, ln1g + (size_t)l * ND, ln1b + (size_t)l * ND, ph);

        tc_gemm_k<0><<<dim3(NTOK / 128, N3D / 128), 256, SMEM_GEMM>>>(
            ph, pqkvT + (size_t)l * N3D * ND, qkvb + (size_t)l * N3D,
            nullptr, pqkv, N3D, ND);

        flash_attn_k<<<dim3(NT / 64, NB * NH), 128, FLASH_SMEM>>>();

        tc_gemm64_k<1><<<dim3(NTOK / 64, ND / 64), 128, SMEM_G64>>>(
            pao, pprojT + (size_t)l * ND * ND, projb + (size_t)l * ND,
            px, px, ND, ND);

        // --- MLP half ---
        ln_k<<<NTOK / 8, 256>>>(px, ln2g + (size_t)l * ND, ln2b + (size_t)l * ND, ph);

        tc_gemm64_k<2><<<dim3(NTOK / 64, N4D / 64), 128, SMEM_G64>>>(
            ph, pfc1T + (size_t)l * N4D * ND, fc1b + (size_t)l * N4D,
            nullptr, pfc1, N4D, ND);

        tc_gemm64_k<1><<<dim3(NTOK / 64, ND / 64), 128, SMEM_G64>>>(
            pfc1, pfc2T + (size_t)l * ND * N4D, fc2b + (size_t)l * ND,
            px, px, ND, N4D);
    }

    // final LN + tied head
    ln_k<<<NTOK / 8, 256>>>(px, lnfg, lnfb, ph);
    tc_gemm_k<3><<<dim3(NTOK / 128, NVP / 128), 256, SMEM_GEMM>>>(
        ph, pwteT, nullptr, nullptr, (float*)d_out, NV, ND);
}